// round 1
// baseline (speedup 1.0000x reference)
#include <cuda_runtime.h>

// ---------------- problem constants ----------------
#define NN    50000
#define EE    800000
#define ET    (EE + NN)     // edges + self loops
#define GG    64
#define FIN   128
#define HID   32
#define HEADS 4
#define F1    (HEADS * HID) // 128
#define OUTD  10
#define NEG   0.2f

// ---------------- device scratch (no allocations allowed) ----------------
__device__ float g_h1  [NN * F1];       // layer-1 transformed features
__device__ float g_as1 [NN * HEADS];
__device__ float g_ad1 [NN * HEADS];
__device__ float g_ew1 [ET * HEADS];    // exp(leaky(logit)) per edge/head
__device__ float g_den1[NN * HEADS];
__device__ float g_out1[NN * F1];       // layer-1 aggregated output
__device__ float g_h2  [NN * HID];
__device__ float g_as2 [NN];
__device__ float g_ad2 [NN];
__device__ float g_ew2 [ET];
__device__ float g_den2[NN];
__device__ float g_out2[NN * HID];
__device__ float g_psum[GG * HID];
__device__ float g_cnt [GG];

__device__ __forceinline__ float lrelu(float v) { return v > 0.f ? v : NEG * v; }

// ---------------- K1: h1 = x @ W1, attention dots, zero-init out1/den1 ----
// block: 128 threads, 8 nodes per block. xs stored transposed: xs[k*8+i].
__global__ void k1_gemm1(const float* __restrict__ x,
                         const float* __restrict__ W1,
                         const float* __restrict__ as1,
                         const float* __restrict__ ad1) {
    __shared__ float xs[FIN * 8];
    const int n0  = blockIdx.x * 8;
    const int tid = threadIdx.x;           // = output column j (0..127)
    #pragma unroll
    for (int i = 0; i < 8; i++)
        xs[tid * 8 + i] = x[(n0 + i) * FIN + tid];
    __syncthreads();

    float acc[8];
    #pragma unroll
    for (int i = 0; i < 8; i++) acc[i] = 0.f;

    #pragma unroll 4
    for (int k = 0; k < FIN; k++) {
        const float w = W1[k * F1 + tid];
        const float4 a = *(const float4*)&xs[k * 8];
        const float4 b = *(const float4*)&xs[k * 8 + 4];
        acc[0] += a.x * w; acc[1] += a.y * w; acc[2] += a.z * w; acc[3] += a.w * w;
        acc[4] += b.x * w; acc[5] += b.y * w; acc[6] += b.z * w; acc[7] += b.w * w;
    }

    const int lane = tid & 31, wid = tid >> 5;  // wid == head
    const float a_s = as1[tid], a_d = ad1[tid];
    #pragma unroll
    for (int i = 0; i < 8; i++) {
        const int n = n0 + i;
        g_h1  [n * F1 + tid] = acc[i];
        g_out1[n * F1 + tid] = 0.f;
        float s = acc[i] * a_s;
        float d = acc[i] * a_d;
        #pragma unroll
        for (int o = 16; o > 0; o >>= 1) {
            s += __shfl_down_sync(0xffffffffu, s, o);
            d += __shfl_down_sync(0xffffffffu, d, o);
        }
        if (lane == 0) {
            g_as1 [n * HEADS + wid] = s;
            g_ad1 [n * HEADS + wid] = d;
            g_den1[n * HEADS + wid] = 0.f;
        }
    }
}

// ---------------- K2: per-edge softmax numerators + denominator (layer 1) --
__global__ void k2_edge1(const int* __restrict__ src, const int* __restrict__ dst) {
    const int e = blockIdx.x * blockDim.x + threadIdx.x;
    if (e >= ET) return;
    int si, di;
    if (e < EE) { si = src[e]; di = dst[e]; }
    else        { si = di = e - EE; }
    const float4 s = *(const float4*)&g_as1[si * 4];
    const float4 d = *(const float4*)&g_ad1[di * 4];
    const float w0 = __expf(lrelu(s.x + d.x));
    const float w1 = __expf(lrelu(s.y + d.y));
    const float w2 = __expf(lrelu(s.z + d.z));
    const float w3 = __expf(lrelu(s.w + d.w));
    *(float4*)&g_ew1[(size_t)e * 4] = make_float4(w0, w1, w2, w3);
    atomicAdd(&g_den1[di * 4 + 0], w0);
    atomicAdd(&g_den1[di * 4 + 1], w1);
    atomicAdd(&g_den1[di * 4 + 2], w2);
    atomicAdd(&g_den1[di * 4 + 3], w3);
}

// ---------------- K3: scatter aggregation (layer 1), warp per edge --------
__global__ void k3_agg1(const int* __restrict__ src, const int* __restrict__ dst) {
    const int w    = (blockIdx.x * blockDim.x + threadIdx.x) >> 5;
    const int lane = threadIdx.x & 31;
    if (w >= ET) return;
    int si, di;
    if (w < EE) { si = src[w]; di = dst[w]; }
    else        { si = di = w - EE; }
    float a4 = 0.f;
    if (lane < 4)
        a4 = g_ew1[(size_t)w * 4 + lane] / g_den1[di * 4 + lane];
    #pragma unroll
    for (int h = 0; h < 4; h++) {
        const float alpha = __shfl_sync(0xffffffffu, a4, h);
        const int f = h * 32 + lane;
        atomicAdd(&g_out1[di * F1 + f], alpha * g_h1[si * F1 + f]);
    }
}

// ---------------- K4: x2 = relu(out1+b1); h2 = x2 @ W2; att dots; zeros ---
// block: 256 threads (8 warps), 32 nodes/block, each warp handles 4 nodes.
__global__ void k4_gemm2(const float* __restrict__ W2,
                         const float* __restrict__ b1,
                         const float* __restrict__ as2,
                         const float* __restrict__ ad2) {
    __shared__ float xs[32 * FIN];
    const int n0  = blockIdx.x * 32;
    const int tid = threadIdx.x;
    for (int idx = tid; idx < 32 * FIN; idx += 256) {
        const int n = n0 + idx / FIN;
        float v = 0.f;
        if (n < NN) {
            v = g_out1[(size_t)n0 * FIN + idx] + b1[idx & (FIN - 1)];
            v = v > 0.f ? v : 0.f;
        }
        xs[idx] = v;
    }
    __syncthreads();

    const int lane = tid & 31, w = tid >> 5;   // lane = output col c
    const float* x0 = &xs[(w * 4 + 0) * FIN];
    const float* x1 = &xs[(w * 4 + 1) * FIN];
    const float* x2 = &xs[(w * 4 + 2) * FIN];
    const float* x3 = &xs[(w * 4 + 3) * FIN];
    float acc[4] = {0.f, 0.f, 0.f, 0.f};
    #pragma unroll 4
    for (int k = 0; k < FIN; k++) {
        const float wt = W2[k * HID + lane];
        acc[0] += x0[k] * wt;
        acc[1] += x1[k] * wt;
        acc[2] += x2[k] * wt;
        acc[3] += x3[k] * wt;
    }
    const float a_s = as2[lane], a_d = ad2[lane];
    #pragma unroll
    for (int j = 0; j < 4; j++) {
        const int n = n0 + w * 4 + j;
        if (n >= NN) break;
        g_h2  [n * HID + lane] = acc[j];
        g_out2[n * HID + lane] = 0.f;
        float s = acc[j] * a_s;
        float d = acc[j] * a_d;
        #pragma unroll
        for (int o = 16; o > 0; o >>= 1) {
            s += __shfl_down_sync(0xffffffffu, s, o);
            d += __shfl_down_sync(0xffffffffu, d, o);
        }
        if (lane == 0) { g_as2[n] = s; g_ad2[n] = d; g_den2[n] = 0.f; }
    }
    if (blockIdx.x == 0) {
        for (int idx = tid; idx < GG * HID; idx += 256) g_psum[idx] = 0.f;
        if (tid < GG) g_cnt[tid] = 0.f;
    }
}

// ---------------- K5: per-edge softmax numerators + denominator (layer 2) --
__global__ void k5_edge2(const int* __restrict__ src, const int* __restrict__ dst) {
    const int e = blockIdx.x * blockDim.x + threadIdx.x;
    if (e >= ET) return;
    int si, di;
    if (e < EE) { si = src[e]; di = dst[e]; }
    else        { si = di = e - EE; }
    const float wv = __expf(lrelu(g_as2[si] + g_ad2[di]));
    g_ew2[e] = wv;
    atomicAdd(&g_den2[di], wv);
}

// ---------------- K6: scatter aggregation (layer 2), warp per edge --------
__global__ void k6_agg2(const int* __restrict__ src, const int* __restrict__ dst) {
    const int w    = (blockIdx.x * blockDim.x + threadIdx.x) >> 5;
    const int lane = threadIdx.x & 31;
    if (w >= ET) return;
    int si, di;
    if (w < EE) { si = src[w]; di = dst[w]; }
    else        { si = di = w - EE; }
    const float alpha = g_ew2[w] / g_den2[di];
    atomicAdd(&g_out2[di * HID + lane], alpha * g_h2[si * HID + lane]);
}

// ---------------- K7: relu(out2+b2) + mean-pool accumulate ----------------
__global__ void k7_pool(const int* __restrict__ batch, const float* __restrict__ b2) {
    const int gtid = blockIdx.x * blockDim.x + threadIdx.x;
    const int n    = gtid >> 5;
    const int lane = gtid & 31;
    if (n >= NN) return;
    float v = g_out2[n * HID + lane] + b2[lane];
    v = v > 0.f ? v : 0.f;
    const int g = batch[n];
    atomicAdd(&g_psum[g * HID + lane], v);
    if (lane == 0) atomicAdd(&g_cnt[g], 1.f);
}

// ---------------- K8: final FC ----------------
__global__ void k8_fc(const float* __restrict__ fcw, const float* __restrict__ fcb,
                      float* __restrict__ out) {
    const int tid = threadIdx.x;
    if (tid >= GG * OUTD) return;
    const int g = tid / OUTD, o = tid % OUTD;
    const float inv = 1.f / fmaxf(g_cnt[g], 1.f);
    float acc = fcb[o];
    #pragma unroll
    for (int c = 0; c < HID; c++)
        acc += g_psum[g * HID + c] * inv * fcw[c * OUTD + o];
    out[tid] = acc;
}

// ---------------- launch ----------------
extern "C" void kernel_launch(void* const* d_in, const int* in_sizes, int n_in,
                              void* d_out, int out_size) {
    const float* x    = (const float*)d_in[0];
    const int*   esrc = (const int*)  d_in[1];
    const int*   edst = (const int*)  d_in[2];
    const int*   batch= (const int*)  d_in[3];
    const float* W1   = (const float*)d_in[4];
    const float* as1  = (const float*)d_in[5];
    const float* ad1  = (const float*)d_in[6];
    const float* b1   = (const float*)d_in[7];
    const float* W2   = (const float*)d_in[8];
    const float* as2  = (const float*)d_in[9];
    const float* ad2  = (const float*)d_in[10];
    const float* b2   = (const float*)d_in[11];
    const float* fcw  = (const float*)d_in[12];
    const float* fcb  = (const float*)d_in[13];
    float* out = (float*)d_out;

    k1_gemm1<<<NN / 8, 128>>>(x, W1, as1, ad1);
    k2_edge1<<<(ET + 255) / 256, 256>>>(esrc, edst);
    k3_agg1 <<<(ET * 32 + 255) / 256, 256>>>(esrc, edst);
    k4_gemm2<<<(NN + 31) / 32, 256>>>(W2, b1, as2, ad2);
    k5_edge2<<<(ET + 255) / 256, 256>>>(esrc, edst);
    k6_agg2 <<<(ET * 32 + 255) / 256, 256>>>(esrc, edst);
    k7_pool <<<(NN * 32 + 255) / 256, 256>>>(batch, b2);
    k8_fc   <<<1, 640>>>(fcw, fcb, out);
}

// round 2
// speedup vs baseline: 1.2405x; 1.2405x over previous
#include <cuda_runtime.h>

// ---------------- problem constants ----------------
#define NN    50000
#define NNP   50016         // NN padded to multiple of 32 (k4 tile reads)
#define EE    800000
#define ET    (EE + NN)     // edges + self loops
#define GG    64
#define FIN   128
#define HID   32
#define HEADS 4
#define F1    (HEADS * HID) // 128
#define OUTD  10
#define NEG   0.2f
#define FULL  0xffffffffu

// ---------------- device scratch (no allocations allowed) ----------------
__device__ float g_h1  [NN * F1];       // layer-1 transformed features
__device__ float g_as1 [NN * HEADS];
__device__ float g_ad1 [NN * HEADS];
__device__ float g_x2  [NNP * F1];      // relu(layer1 out + b1)  (padded)
__device__ float g_h2  [NN * HID];
__device__ float g_as2 [NN];
__device__ float g_ad2 [NN];
__device__ float g_psum[GG * HID];
__device__ float g_cnt [GG];
// CSR-by-destination
__device__ int   g_deg   [NN];
__device__ int   g_cursor[NN];
__device__ int   g_rs    [NN + 1];
__device__ int   g_es    [ET];          // src node per CSR slot

__device__ __forceinline__ float lrelu(float v) { return v > 0.f ? v : NEG * v; }

// ---------------- K0: init counters + pooled accumulators ----------------
__global__ void k_init() {
    const int i = blockIdx.x * blockDim.x + threadIdx.x;
    if (i < NN) { g_deg[i] = 1; g_cursor[i] = 0; }  // 1 = self loop
    if (i < GG * HID) g_psum[i] = 0.f;
    if (i < GG) g_cnt[i] = 0.f;
}

// ---------------- K0b: count in-degree ----------------
__global__ void k_count(const int* __restrict__ dst) {
    const int e = blockIdx.x * blockDim.x + threadIdx.x;
    if (e < EE) atomicAdd(&g_deg[dst[e]], 1);
}

// ---------------- K0c: exclusive scan of deg -> row starts (1 block) -----
__global__ void k_scan() {
    __shared__ int wsum[32];
    __shared__ int sbase;
    const int tid = threadIdx.x, lane = tid & 31, wid = tid >> 5;
    if (tid == 0) sbase = 0;
    __syncthreads();
    const int nchunks = (NN + 1023) / 1024;
    for (int c = 0; c < nchunks; c++) {
        const int i = c * 1024 + tid;
        int s = (i < NN) ? g_deg[i] : 0;
        #pragma unroll
        for (int o = 1; o < 32; o <<= 1) {
            const int t = __shfl_up_sync(FULL, s, o);
            if (lane >= o) s += t;
        }
        if (lane == 31) wsum[wid] = s;
        __syncthreads();
        if (wid == 0) {
            int ws = wsum[lane];
            #pragma unroll
            for (int o = 1; o < 32; o <<= 1) {
                const int t = __shfl_up_sync(FULL, ws, o);
                if (lane >= o) ws += t;
            }
            wsum[lane] = ws;
        }
        __syncthreads();
        const int base = sbase + (wid ? wsum[wid - 1] : 0);
        const int chunk_total = wsum[31];
        if (i < NN) g_rs[i + 1] = base + s;
        __syncthreads();
        if (tid == 0) sbase += chunk_total;
        __syncthreads();
    }
    if (tid == 0) g_rs[0] = 0;
}

// ---------------- K0d: scatter edges into CSR slots ----------------------
__global__ void k_scatter(const int* __restrict__ src, const int* __restrict__ dst) {
    const int e = blockIdx.x * blockDim.x + threadIdx.x;
    if (e >= ET) return;
    int si, di;
    if (e < EE) { si = src[e]; di = dst[e]; }
    else        { si = di = e - EE; }
    const int p = atomicAdd(&g_cursor[di], 1);
    g_es[g_rs[di] + p] = si;
}

// ---------------- K1: h1 = x @ W1 + attention dots ----------------------
__global__ void k1_gemm1(const float* __restrict__ x,
                         const float* __restrict__ W1,
                         const float* __restrict__ as1,
                         const float* __restrict__ ad1) {
    __shared__ float xs[FIN * 8];
    const int n0  = blockIdx.x * 8;
    const int tid = threadIdx.x;           // = output column j (0..127)
    #pragma unroll
    for (int i = 0; i < 8; i++)
        xs[tid * 8 + i] = x[(n0 + i) * FIN + tid];
    __syncthreads();

    float acc[8];
    #pragma unroll
    for (int i = 0; i < 8; i++) acc[i] = 0.f;

    #pragma unroll 4
    for (int k = 0; k < FIN; k++) {
        const float w = W1[k * F1 + tid];
        const float4 a = *(const float4*)&xs[k * 8];
        const float4 b = *(const float4*)&xs[k * 8 + 4];
        acc[0] += a.x * w; acc[1] += a.y * w; acc[2] += a.z * w; acc[3] += a.w * w;
        acc[4] += b.x * w; acc[5] += b.y * w; acc[6] += b.z * w; acc[7] += b.w * w;
    }

    const int lane = tid & 31, wid = tid >> 5;  // wid == head
    const float a_s = as1[tid], a_d = ad1[tid];
    #pragma unroll
    for (int i = 0; i < 8; i++) {
        const int n = n0 + i;
        g_h1[n * F1 + tid] = acc[i];
        float s = acc[i] * a_s;
        float d = acc[i] * a_d;
        #pragma unroll
        for (int o = 16; o > 0; o >>= 1) {
            s += __shfl_down_sync(FULL, s, o);
            d += __shfl_down_sync(FULL, d, o);
        }
        if (lane == 0) {
            g_as1[n * HEADS + wid] = s;
            g_ad1[n * HEADS + wid] = d;
        }
    }
}

// ---------------- K_AGG1: gather-aggregate layer 1 (warp per dst node) ----
// Computes out = (Σ_e w_e h1[src_e]) / (Σ_e w_e), fuses +b1, relu -> g_x2.
__global__ void k_agg1(const float* __restrict__ b1) {
    const int w    = blockIdx.x * 32 + (threadIdx.x >> 5);
    const int lane = threadIdx.x & 31;
    if (w >= NN) return;
    const int di  = w;
    const int beg = g_rs[di], end = g_rs[di + 1];
    const float ad = (lane < 4) ? g_ad1[di * 4 + lane] : 0.f;

    float acc0 = 0.f, acc1 = 0.f, acc2 = 0.f, acc3 = 0.f;
    float den0 = 0.f, den1 = 0.f, den2 = 0.f, den3 = 0.f;

    for (int p0 = beg; p0 < end; p0 += 32) {
        const int m  = min(32, end - p0);
        const int sl = (p0 + lane < end) ? g_es[p0 + lane] : 0;
        for (int j = 0; j < m; j++) {
            const int si = __shfl_sync(FULL, sl, j);
            float wv = 0.f;
            if (lane < 4) wv = __expf(lrelu(g_as1[si * 4 + lane] + ad));
            const float w0 = __shfl_sync(FULL, wv, 0);
            const float w1 = __shfl_sync(FULL, wv, 1);
            const float w2 = __shfl_sync(FULL, wv, 2);
            const float w3 = __shfl_sync(FULL, wv, 3);
            const float* hr = &g_h1[(size_t)si * F1];
            acc0 += w0 * hr[lane];
            acc1 += w1 * hr[32 + lane];
            acc2 += w2 * hr[64 + lane];
            acc3 += w3 * hr[96 + lane];
            den0 += w0; den1 += w1; den2 += w2; den3 += w3;
        }
    }
    float* xo = &g_x2[(size_t)di * F1];
    xo[lane]      = fmaxf(acc0 / den0 + b1[lane],      0.f);
    xo[32 + lane] = fmaxf(acc1 / den1 + b1[32 + lane], 0.f);
    xo[64 + lane] = fmaxf(acc2 / den2 + b1[64 + lane], 0.f);
    xo[96 + lane] = fmaxf(acc3 / den3 + b1[96 + lane], 0.f);
}

// ---------------- K4: h2 = x2 @ W2 + attention dots ----------------------
// block: 256 threads (8 warps), 32 nodes/block, each warp handles 4 nodes.
__global__ void k4_gemm2(const float* __restrict__ W2,
                         const float* __restrict__ as2,
                         const float* __restrict__ ad2) {
    __shared__ float xs[32 * FIN];
    const int n0  = blockIdx.x * 32;
    const int tid = threadIdx.x;
    const float4* src4 = (const float4*)&g_x2[(size_t)n0 * FIN];
    float4* xs4 = (float4*)xs;
    #pragma unroll
    for (int it = 0; it < 4; it++)
        xs4[tid + it * 256] = src4[tid + it * 256];   // padded g_x2: safe
    __syncthreads();

    const int lane = tid & 31, w = tid >> 5;   // lane = output col c
    const float4* x0 = (const float4*)&xs[(w * 4 + 0) * FIN];
    const float4* x1 = (const float4*)&xs[(w * 4 + 1) * FIN];
    const float4* x2 = (const float4*)&xs[(w * 4 + 2) * FIN];
    const float4* x3 = (const float4*)&xs[(w * 4 + 3) * FIN];
    float acc[4] = {0.f, 0.f, 0.f, 0.f};
    #pragma unroll 8
    for (int k4i = 0; k4i < FIN / 4; k4i++) {
        const float wt0 = W2[(k4i * 4 + 0) * HID + lane];
        const float wt1 = W2[(k4i * 4 + 1) * HID + lane];
        const float wt2 = W2[(k4i * 4 + 2) * HID + lane];
        const float wt3 = W2[(k4i * 4 + 3) * HID + lane];
        const float4 a = x0[k4i], b = x1[k4i], c = x2[k4i], d = x3[k4i];
        acc[0] += a.x * wt0 + a.y * wt1 + a.z * wt2 + a.w * wt3;
        acc[1] += b.x * wt0 + b.y * wt1 + b.z * wt2 + b.w * wt3;
        acc[2] += c.x * wt0 + c.y * wt1 + c.z * wt2 + c.w * wt3;
        acc[3] += d.x * wt0 + d.y * wt1 + d.z * wt2 + d.w * wt3;
    }
    const float a_s = as2[lane], a_d = ad2[lane];
    #pragma unroll
    for (int j = 0; j < 4; j++) {
        const int n = n0 + w * 4 + j;
        if (n >= NN) break;
        g_h2[n * HID + lane] = acc[j];
        float s = acc[j] * a_s;
        float d = acc[j] * a_d;
        #pragma unroll
        for (int o = 16; o > 0; o >>= 1) {
            s += __shfl_down_sync(FULL, s, o);
            d += __shfl_down_sync(FULL, d, o);
        }
        if (lane == 0) { g_as2[n] = s; g_ad2[n] = d; }
    }
}

// ---------------- K_AGG2: gather layer 2 + relu + mean-pool accumulate ----
__global__ void k_agg2(const int* __restrict__ batch, const float* __restrict__ b2) {
    const int w    = blockIdx.x * 32 + (threadIdx.x >> 5);
    const int lane = threadIdx.x & 31;
    if (w >= NN) return;
    const int di  = w;
    const int beg = g_rs[di], end = g_rs[di + 1];
    const float ad = g_ad2[di];

    float acc = 0.f, den = 0.f;
    for (int p0 = beg; p0 < end; p0 += 32) {
        const int m  = min(32, end - p0);
        const int sl = (p0 + lane < end) ? g_es[p0 + lane] : 0;
        for (int j = 0; j < m; j++) {
            const int si = __shfl_sync(FULL, sl, j);
            float wv = 0.f;
            if (lane == 0) wv = __expf(lrelu(g_as2[si] + ad));
            wv = __shfl_sync(FULL, wv, 0);
            acc += wv * g_h2[si * HID + lane];
            den += wv;
        }
    }
    const float v = fmaxf(acc / den + b2[lane], 0.f);
    const int g = batch[di];
    atomicAdd(&g_psum[g * HID + lane], v);
    if (lane == 0) atomicAdd(&g_cnt[g], 1.f);
}

// ---------------- K8: final FC ----------------
__global__ void k8_fc(const float* __restrict__ fcw, const float* __restrict__ fcb,
                      float* __restrict__ out) {
    const int tid = threadIdx.x;
    if (tid >= GG * OUTD) return;
    const int g = tid / OUTD, o = tid % OUTD;
    const float inv = 1.f / fmaxf(g_cnt[g], 1.f);
    float acc = fcb[o];
    #pragma unroll
    for (int c = 0; c < HID; c++)
        acc += g_psum[g * HID + c] * inv * fcw[c * OUTD + o];
    out[tid] = acc;
}

// ---------------- launch ----------------
extern "C" void kernel_launch(void* const* d_in, const int* in_sizes, int n_in,
                              void* d_out, int out_size) {
    const float* x    = (const float*)d_in[0];
    const int*   esrc = (const int*)  d_in[1];
    const int*   edst = (const int*)  d_in[2];
    const int*   batch= (const int*)  d_in[3];
    const float* W1   = (const float*)d_in[4];
    const float* as1  = (const float*)d_in[5];
    const float* ad1  = (const float*)d_in[6];
    const float* b1   = (const float*)d_in[7];
    const float* W2   = (const float*)d_in[8];
    const float* as2  = (const float*)d_in[9];
    const float* ad2  = (const float*)d_in[10];
    const float* b2   = (const float*)d_in[11];
    const float* fcw  = (const float*)d_in[12];
    const float* fcb  = (const float*)d_in[13];
    float* out = (float*)d_out;

    k_init   <<<(NN + 255) / 256, 256>>>();
    k_count  <<<(EE + 255) / 256, 256>>>(edst);
    k_scan   <<<1, 1024>>>();
    k_scatter<<<(ET + 255) / 256, 256>>>(esrc, edst);
    k1_gemm1 <<<NN / 8, 128>>>(x, W1, as1, ad1);
    k_agg1   <<<(NN + 31) / 32, 1024>>>(b1);
    k4_gemm2 <<<(NN + 31) / 32, 256>>>(W2, as2, ad2);
    k_agg2   <<<(NN + 31) / 32, 1024>>>(batch, b2);
    k8_fc    <<<1, 640>>>(fcw, fcb, out);
}

// round 4
// speedup vs baseline: 1.3105x; 1.0564x over previous
#include <cuda_runtime.h>

// ---------------- problem constants ----------------
#define NN    50000
#define NNP   50016         // NN padded to multiple of 32 (k4 tile reads)
#define EE    800000
#define ET    (EE + NN)     // edges + self loops
#define GG    64
#define FIN   128
#define HID   32
#define HEADS 4
#define F1    (HEADS * HID) // 128
#define OUTD  10
#define NEG   0.2f
#define FULL  0xffffffffu

// ---------------- device scratch (no allocations allowed) ----------------
__device__ float g_h1  [NN * F1];       // layer-1 transformed features
__device__ float g_as1 [NN * HEADS];
__device__ float g_ad1 [NN * HEADS];
__device__ float g_x2  [NNP * F1];      // relu(layer1 out + b1)  (padded)
__device__ float g_h2  [NN * HID];
__device__ float g_as2 [NN];
__device__ float g_ad2 [NN];
__device__ float g_psum[GG * HID];
__device__ float g_cnt [GG];
// CSR-by-destination
__device__ int   g_deg   [NN];
__device__ int   g_cursor[NN];          // running slot cursor (starts at rs)
__device__ int   g_rs    [NN + 1];
__device__ int   g_es    [ET];          // src node per CSR slot

__device__ __forceinline__ float lrelu(float v) { return v > 0.f ? v : NEG * v; }

// ---------------- K0: init counters + pooled accumulators ----------------
__global__ void k_init() {
    const int i = blockIdx.x * blockDim.x + threadIdx.x;
    if (i < NN) g_deg[i] = 1;          // 1 = self loop
    if (i < GG * HID) g_psum[i] = 0.f;
    if (i < GG) g_cnt[i] = 0.f;
}

// ---------------- K0b: count in-degree ----------------
__global__ void k_count(const int* __restrict__ dst) {
    const int e = blockIdx.x * blockDim.x + threadIdx.x;
    if (e < EE) atomicAdd(&g_deg[dst[e]], 1);
}

// ---------------- K0c: exclusive scan of deg -> row starts + cursor init --
__global__ void k_scan() {
    __shared__ int wsum[32];
    __shared__ int sbase;
    const int tid = threadIdx.x, lane = tid & 31, wid = tid >> 5;
    if (tid == 0) { sbase = 0; g_rs[0] = 0; }
    __syncthreads();
    const int nchunks = (NN + 1023) / 1024;
    for (int c = 0; c < nchunks; c++) {
        const int i = c * 1024 + tid;
        int s = (i < NN) ? g_deg[i] : 0;
        #pragma unroll
        for (int o = 1; o < 32; o <<= 1) {
            const int t = __shfl_up_sync(FULL, s, o);
            if (lane >= o) s += t;
        }
        if (lane == 31) wsum[wid] = s;
        __syncthreads();
        if (wid == 0) {
            int ws = wsum[lane];
            #pragma unroll
            for (int o = 1; o < 32; o <<= 1) {
                const int t = __shfl_up_sync(FULL, ws, o);
                if (lane >= o) ws += t;
            }
            wsum[lane] = ws;
        }
        __syncthreads();
        const int base = sbase + (wid ? wsum[wid - 1] : 0);
        const int chunk_total = wsum[31];
        if (i < NN) g_rs[i + 1] = base + s;
        __syncthreads();
        if (tid == 0) sbase += chunk_total;
        __syncthreads();
    }
    // cursor starts at row start (all rs writes done by this block)
    for (int i = tid; i < NN; i += 1024) g_cursor[i] = g_rs[i];
}

// ---------------- K0d: scatter edges into CSR slots ----------------------
__global__ void k_scatter(const int* __restrict__ src, const int* __restrict__ dst) {
    const int e = blockIdx.x * blockDim.x + threadIdx.x;
    if (e >= ET) return;
    int si, di;
    if (e < EE) { si = src[e]; di = dst[e]; }
    else        { si = di = e - EE; }
    g_es[atomicAdd(&g_cursor[di], 1)] = si;
}

// ---------------- K1: h1 = x @ W1 + attention dots (16 nodes/block) ------
__global__ void k1_gemm1(const float* __restrict__ x,
                         const float* __restrict__ W1,
                         const float* __restrict__ as1,
                         const float* __restrict__ ad1) {
    __shared__ float xs[FIN * 16];
    const int n0  = blockIdx.x * 16;
    const int tid = threadIdx.x;           // = output column j (0..127)
    #pragma unroll
    for (int i = 0; i < 16; i++)
        xs[tid * 16 + i] = x[(n0 + i) * FIN + tid];
    __syncthreads();

    float acc[16];
    #pragma unroll
    for (int i = 0; i < 16; i++) acc[i] = 0.f;

    #pragma unroll 2
    for (int k = 0; k < FIN; k++) {
        const float w = W1[k * F1 + tid];
        const float4* xr = (const float4*)&xs[k * 16];
        #pragma unroll
        for (int q = 0; q < 4; q++) {
            const float4 a = xr[q];
            acc[q * 4 + 0] += a.x * w;
            acc[q * 4 + 1] += a.y * w;
            acc[q * 4 + 2] += a.z * w;
            acc[q * 4 + 3] += a.w * w;
        }
    }

    const int lane = tid & 31, wid = tid >> 5;  // wid == head
    const float a_s = as1[tid], a_d = ad1[tid];
    #pragma unroll
    for (int i = 0; i < 16; i++) {
        const int n = n0 + i;
        g_h1[n * F1 + tid] = acc[i];
        float s = acc[i] * a_s;
        float d = acc[i] * a_d;
        #pragma unroll
        for (int o = 16; o > 0; o >>= 1) {
            s += __shfl_down_sync(FULL, s, o);
            d += __shfl_down_sync(FULL, d, o);
        }
        if (lane == 0) {
            g_as1[n * HEADS + wid] = s;
            g_ad1[n * HEADS + wid] = d;
        }
    }
}

// ---------------- K_AGG1: gather layer 1, warp per (dst, head) -----------
__global__ void k_agg1(const float* __restrict__ b1) {
    const int gw   = blockIdx.x * 8 + (threadIdx.x >> 5);
    const int lane = threadIdx.x & 31;
    const int di   = gw >> 2, h = gw & 3;
    if (di >= NN) return;
    const int   beg  = g_rs[di], end = g_rs[di + 1];
    const float ad   = g_ad1[di * 4 + h];
    const int   hoff = h * 32;

    float acc0 = 0.f, acc1 = 0.f, acc2 = 0.f, acc3 = 0.f, den = 0.f;

    for (int p0 = beg; p0 < end; p0 += 32) {
        const int m = min(32, end - p0);
        int   sl = 0;
        float wv = 0.f;
        if (p0 + lane < end) {
            sl = g_es[p0 + lane];
            wv = __expf(lrelu(g_as1[sl * 4 + h] + ad));
            den += wv;
        }
        int j = 0;
        for (; j + 4 <= m; j += 4) {
            const int   s0 = __shfl_sync(FULL, sl, j);
            const int   s1 = __shfl_sync(FULL, sl, j + 1);
            const int   s2 = __shfl_sync(FULL, sl, j + 2);
            const int   s3 = __shfl_sync(FULL, sl, j + 3);
            const float w0 = __shfl_sync(FULL, wv, j);
            const float w1 = __shfl_sync(FULL, wv, j + 1);
            const float w2 = __shfl_sync(FULL, wv, j + 2);
            const float w3 = __shfl_sync(FULL, wv, j + 3);
            const float l0 = g_h1[(size_t)s0 * F1 + hoff + lane];
            const float l1 = g_h1[(size_t)s1 * F1 + hoff + lane];
            const float l2 = g_h1[(size_t)s2 * F1 + hoff + lane];
            const float l3 = g_h1[(size_t)s3 * F1 + hoff + lane];
            acc0 += w0 * l0; acc1 += w1 * l1; acc2 += w2 * l2; acc3 += w3 * l3;
        }
        for (; j < m; j++) {
            const int   s0 = __shfl_sync(FULL, sl, j);
            const float w0 = __shfl_sync(FULL, wv, j);
            acc0 += w0 * g_h1[(size_t)s0 * F1 + hoff + lane];
        }
    }
    #pragma unroll
    for (int o = 16; o > 0; o >>= 1) den += __shfl_xor_sync(FULL, den, o);
    const float acc = (acc0 + acc1) + (acc2 + acc3);
    g_x2[(size_t)di * F1 + hoff + lane] =
        fmaxf(acc / den + b1[hoff + lane], 0.f);
}

// ---------------- K4: h2 = x2 @ W2 + attention dots ----------------------
// block: 256 threads (8 warps), 32 nodes/block, each warp handles 4 nodes.
__global__ void k4_gemm2(const float* __restrict__ W2,
                         const float* __restrict__ as2,
                         const float* __restrict__ ad2) {
    __shared__ float xs[32 * FIN];
    const int n0  = blockIdx.x * 32;
    const int tid = threadIdx.x;
    const float4* src4 = (const float4*)&g_x2[(size_t)n0 * FIN];
    float4* xs4 = (float4*)xs;
    #pragma unroll
    for (int it = 0; it < 4; it++)
        xs4[tid + it * 256] = src4[tid + it * 256];   // padded g_x2: safe
    __syncthreads();

    const int lane = tid & 31, w = tid >> 5;   // lane = output col c
    const float4* x0 = (const float4*)&xs[(w * 4 + 0) * FIN];
    const float4* x1 = (const float4*)&xs[(w * 4 + 1) * FIN];
    const float4* x2 = (const float4*)&xs[(w * 4 + 2) * FIN];
    const float4* x3 = (const float4*)&xs[(w * 4 + 3) * FIN];
    float acc[4] = {0.f, 0.f, 0.f, 0.f};
    #pragma unroll 8
    for (int k4i = 0; k4i < FIN / 4; k4i++) {
        const float wt0 = W2[(k4i * 4 + 0) * HID + lane];
        const float wt1 = W2[(k4i * 4 + 1) * HID + lane];
        const float wt2 = W2[(k4i * 4 + 2) * HID + lane];
        const float wt3 = W2[(k4i * 4 + 3) * HID + lane];
        const float4 a = x0[k4i], b = x1[k4i], c = x2[k4i], d = x3[k4i];
        acc[0] += a.x * wt0 + a.y * wt1 + a.z * wt2 + a.w * wt3;
        acc[1] += b.x * wt0 + b.y * wt1 + b.z * wt2 + b.w * wt3;
        acc[2] += c.x * wt0 + c.y * wt1 + c.z * wt2 + c.w * wt3;
        acc[3] += d.x * wt0 + d.y * wt1 + d.z * wt2 + d.w * wt3;
    }
    const float a_s = as2[lane], a_d = ad2[lane];
    #pragma unroll
    for (int j = 0; j < 4; j++) {
        const int n = n0 + w * 4 + j;
        if (n >= NN) break;
        g_h2[n * HID + lane] = acc[j];
        float s = acc[j] * a_s;
        float d = acc[j] * a_d;
        #pragma unroll
        for (int o = 16; o > 0; o >>= 1) {
            s += __shfl_down_sync(FULL, s, o);
            d += __shfl_down_sync(FULL, d, o);
        }
        if (lane == 0) { g_as2[n] = s; g_ad2[n] = d; }
    }
}

// ---------------- K_AGG2: gather layer 2 + relu + mean-pool accumulate ----
__global__ void k_agg2(const int* __restrict__ batch, const float* __restrict__ b2) {
    const int di   = blockIdx.x * 8 + (threadIdx.x >> 5);
    const int lane = threadIdx.x & 31;
    if (di >= NN) return;
    const int   beg = g_rs[di], end = g_rs[di + 1];
    const float ad  = g_ad2[di];

    float acc0 = 0.f, acc1 = 0.f, acc2 = 0.f, acc3 = 0.f, den = 0.f;
    for (int p0 = beg; p0 < end; p0 += 32) {
        const int m = min(32, end - p0);
        int   sl = 0;
        float wv = 0.f;
        if (p0 + lane < end) {
            sl = g_es[p0 + lane];
            wv = __expf(lrelu(g_as2[sl] + ad));
            den += wv;
        }
        int j = 0;
        for (; j + 4 <= m; j += 4) {
            const int   s0 = __shfl_sync(FULL, sl, j);
            const int   s1 = __shfl_sync(FULL, sl, j + 1);
            const int   s2 = __shfl_sync(FULL, sl, j + 2);
            const int   s3 = __shfl_sync(FULL, sl, j + 3);
            const float w0 = __shfl_sync(FULL, wv, j);
            const float w1 = __shfl_sync(FULL, wv, j + 1);
            const float w2 = __shfl_sync(FULL, wv, j + 2);
            const float w3 = __shfl_sync(FULL, wv, j + 3);
            const float l0 = g_h2[s0 * HID + lane];
            const float l1 = g_h2[s1 * HID + lane];
            const float l2 = g_h2[s2 * HID + lane];
            const float l3 = g_h2[s3 * HID + lane];
            acc0 += w0 * l0; acc1 += w1 * l1; acc2 += w2 * l2; acc3 += w3 * l3;
        }
        for (; j < m; j++) {
            const int   s0 = __shfl_sync(FULL, sl, j);
            const float w0 = __shfl_sync(FULL, wv, j);
            acc0 += w0 * g_h2[s0 * HID + lane];
        }
    }
    #pragma unroll
    for (int o = 16; o > 0; o >>= 1) den += __shfl_xor_sync(FULL, den, o);
    const float acc = (acc0 + acc1) + (acc2 + acc3);
    const float v = fmaxf(acc / den + b2[lane], 0.f);
    const int g = batch[di];
    atomicAdd(&g_psum[g * HID + lane], v);
    if (lane == 0) atomicAdd(&g_cnt[g], 1.f);
}

// ---------------- K8: final FC ----------------
__global__ void k8_fc(const float* __restrict__ fcw, const float* __restrict__ fcb,
                      float* __restrict__ out) {
    const int tid = threadIdx.x;
    if (tid >= GG * OUTD) return;
    const int g = tid / OUTD, o = tid % OUTD;
    const float inv = 1.f / fmaxf(g_cnt[g], 1.f);
    float acc = fcb[o];
    #pragma unroll
    for (int c = 0; c < HID; c++)
        acc += g_psum[g * HID + c] * inv * fcw[c * OUTD + o];
    out[tid] = acc;
}

// ---------------- launch ----------------
extern "C" void kernel_launch(void* const* d_in, const int* in_sizes, int n_in,
                              void* d_out, int out_size) {
    const float* x    = (const float*)d_in[0];
    const int*   esrc = (const int*)  d_in[1];
    const int*   edst = (const int*)  d_in[2];
    const int*   batch= (const int*)  d_in[3];
    const float* W1   = (const float*)d_in[4];
    const float* as1  = (const float*)d_in[5];
    const float* ad1  = (const float*)d_in[6];
    const float* b1   = (const float*)d_in[7];
    const float* W2   = (const float*)d_in[8];
    const float* as2  = (const float*)d_in[9];
    const float* ad2  = (const float*)d_in[10];
    const float* b2   = (const float*)d_in[11];
    const float* fcw  = (const float*)d_in[12];
    const float* fcb  = (const float*)d_in[13];
    float* out = (float*)d_out;

    k_init   <<<(NN + 255) / 256, 256>>>();
    k_count  <<<(EE + 255) / 256, 256>>>(edst);
    k_scan   <<<1, 1024>>>();
    k_scatter<<<(ET + 255) / 256, 256>>>(esrc, edst);
    k1_gemm1 <<<(NN + 15) / 16, 128>>>(x, W1, as1, ad1);
    k_agg1   <<<(NN * 4 + 7) / 8, 256>>>(b1);
    k4_gemm2 <<<(NN + 31) / 32, 256>>>(W2, as2, ad2);
    k_agg2   <<<(NN + 7) / 8, 256>>>(batch, b2);
    k8_fc    <<<1, 640>>>(fcw, fcb, out);
}

// round 6
// speedup vs baseline: 1.6722x; 1.2761x over previous
#include <cuda_runtime.h>

// ---------------- problem constants ----------------
#define NN    50000
#define NNP   50016         // NN padded to multiple of 32 (k4 tile reads)
#define EE    800000
#define ET    (EE + NN)     // edges + self loops
#define GG    64
#define FIN   128
#define HID   32
#define HEADS 4
#define F1    (HEADS * HID) // 128
#define OUTD  10
#define NEG   0.2f
#define FULL  0xffffffffu
#define NB    196           // scan blocks: 196*256 = 50176 >= NN

// ---------------- device scratch (no allocations allowed) ----------------
__device__ float g_h1  [NN * F1];       // layer-1 transformed features
__device__ float g_as1 [NN * HEADS];
__device__ float g_ad1 [NN * HEADS];
__device__ float g_x2  [NNP * F1];      // relu(layer1 out + b1)  (padded)
__device__ float g_h2  [NN * HID];
__device__ float g_as2 [NN];
__device__ float g_ad2 [NN];
__device__ float g_psum[GG * HID];
__device__ float g_cnt [GG];
// CSR-by-destination
__device__ int   g_deg   [NN];
__device__ int   g_cursor[NN];
__device__ int   g_rs    [NN + 1];
__device__ int   g_es    [ET];          // src node per CSR slot
__device__ int   g_ed    [ET];          // dst node per CSR slot
__device__ float g_ew4 [(ET + 8) * 4];  // layer-1 weights, 4 heads/slot (padded)
__device__ float g_ew2 [ET + 32];       // layer-2 weights (padded)
__device__ int   g_bsum[NB];
__device__ int   g_boff[NB];

__device__ __forceinline__ float lrelu(float v) { return v > 0.f ? v : NEG * v; }

// ---------------- K0: init counters + pooled accumulators ----------------
__global__ void k_init() {
    const int i = blockIdx.x * blockDim.x + threadIdx.x;
    if (i < NN) g_deg[i] = 1;          // 1 = self loop
    if (i < GG * HID) g_psum[i] = 0.f;
    if (i < GG) g_cnt[i] = 0.f;
}

// ---------------- K0b: count in-degree ----------------
__global__ void k_count(const int* __restrict__ dst) {
    const int e = blockIdx.x * blockDim.x + threadIdx.x;
    if (e < EE) atomicAdd(&g_deg[dst[e]], 1);
}

// ---------------- scan 1: per-block sums ----------------
__global__ void k_scan1() {
    __shared__ int ws[8];
    const int tid = threadIdx.x, lane = tid & 31, wid = tid >> 5;
    const int i = blockIdx.x * 256 + tid;
    int s = (i < NN) ? g_deg[i] : 0;
    #pragma unroll
    for (int o = 16; o; o >>= 1) s += __shfl_down_sync(FULL, s, o);
    if (lane == 0) ws[wid] = s;
    __syncthreads();
    if (wid == 0) {
        int t = (lane < 8) ? ws[lane] : 0;
        #pragma unroll
        for (int o = 4; o; o >>= 1) t += __shfl_down_sync(FULL, t, o);
        if (lane == 0) g_bsum[blockIdx.x] = t;
    }
}

// ---------------- scan 2: exclusive scan of block sums (1 block) ---------
__global__ void k_scan2() {
    __shared__ int ws[8];
    const int tid = threadIdx.x, lane = tid & 31, wid = tid >> 5;
    const int v = (tid < NB) ? g_bsum[tid] : 0;
    int s = v;
    #pragma unroll
    for (int o = 1; o < 32; o <<= 1) {
        const int t = __shfl_up_sync(FULL, s, o);
        if (lane >= o) s += t;
    }
    if (lane == 31) ws[wid] = s;
    __syncthreads();
    if (wid == 0) {
        int t = (lane < 8) ? ws[lane] : 0;
        #pragma unroll
        for (int o = 1; o < 8; o <<= 1) {
            const int u = __shfl_up_sync(FULL, t, o);
            if (lane >= o) t += u;
        }
        if (lane < 8) ws[lane] = t;
    }
    __syncthreads();
    const int base = wid ? ws[wid - 1] : 0;
    if (tid < NB) g_boff[tid] = base + s - v;   // exclusive
}

// ---------------- scan 3: block prefix + rs + cursor ----------------
__global__ void k_scan3() {
    __shared__ int ws[8];
    const int tid = threadIdx.x, lane = tid & 31, wid = tid >> 5;
    const int i = blockIdx.x * 256 + tid;
    const int v = (i < NN) ? g_deg[i] : 0;
    int s = v;
    #pragma unroll
    for (int o = 1; o < 32; o <<= 1) {
        const int t = __shfl_up_sync(FULL, s, o);
        if (lane >= o) s += t;
    }
    if (lane == 31) ws[wid] = s;
    __syncthreads();
    if (wid == 0) {
        int t = (lane < 8) ? ws[lane] : 0;
        #pragma unroll
        for (int o = 1; o < 8; o <<= 1) {
            const int u = __shfl_up_sync(FULL, t, o);
            if (lane >= o) t += u;
        }
        if (lane < 8) ws[lane] = t;
    }
    __syncthreads();
    const int incl = (wid ? ws[wid - 1] : 0) + s + g_boff[blockIdx.x];
    if (i < NN) { g_rs[i + 1] = incl; g_cursor[i] = incl - v; }
    if (i == 0) g_rs[0] = 0;
}

// ---------------- K1: h1 = x @ W1 + attention dots (16 nodes/block) ------
__global__ void k1_gemm1(const float* __restrict__ x,
                         const float* __restrict__ W1,
                         const float* __restrict__ as1,
                         const float* __restrict__ ad1) {
    __shared__ float xs[FIN * 16];
    const int n0  = blockIdx.x * 16;
    const int tid = threadIdx.x;           // = output column j (0..127)
    #pragma unroll
    for (int i = 0; i < 16; i++)
        xs[tid * 16 + i] = x[(n0 + i) * FIN + tid];
    __syncthreads();

    float acc[16];
    #pragma unroll
    for (int i = 0; i < 16; i++) acc[i] = 0.f;

    #pragma unroll 2
    for (int k = 0; k < FIN; k++) {
        const float w = W1[k * F1 + tid];
        const float4* xr = (const float4*)&xs[k * 16];
        #pragma unroll
        for (int q = 0; q < 4; q++) {
            const float4 a = xr[q];
            acc[q * 4 + 0] += a.x * w;
            acc[q * 4 + 1] += a.y * w;
            acc[q * 4 + 2] += a.z * w;
            acc[q * 4 + 3] += a.w * w;
        }
    }

    const int lane = tid & 31, wid = tid >> 5;  // wid == head
    const float a_s = as1[tid], a_d = ad1[tid];
    #pragma unroll
    for (int i = 0; i < 16; i++) {
        const int n = n0 + i;
        g_h1[n * F1 + tid] = acc[i];
        float s = acc[i] * a_s;
        float d = acc[i] * a_d;
        #pragma unroll
        for (int o = 16; o > 0; o >>= 1) {
            s += __shfl_down_sync(FULL, s, o);
            d += __shfl_down_sync(FULL, d, o);
        }
        if (lane == 0) {
            g_as1[n * HEADS + wid] = s;
            g_ad1[n * HEADS + wid] = d;
        }
    }
}

// ---------------- K_SCAT: scatter into CSR + layer-1 edge weights --------
__global__ void k_scatter(const int* __restrict__ src, const int* __restrict__ dst) {
    const int e = blockIdx.x * blockDim.x + threadIdx.x;
    if (e >= ET) return;
    int si, di;
    if (e < EE) { si = src[e]; di = dst[e]; }
    else        { si = di = e - EE; }
    const int slot = atomicAdd(&g_cursor[di], 1);
    g_es[slot] = si;
    g_ed[slot] = di;
    const float4 s4 = ((const float4*)g_as1)[si];
    const float4 d4 = ((const float4*)g_ad1)[di];
    float4 w;
    w.x = __expf(lrelu(s4.x + d4.x));
    w.y = __expf(lrelu(s4.y + d4.y));
    w.z = __expf(lrelu(s4.z + d4.z));
    w.w = __expf(lrelu(s4.w + d4.w));
    ((float4*)g_ew4)[slot] = w;
}

// ---------------- K_AGG1: gather layer 1, warp per dst, float4/lane ------
__global__ void k_agg1(const float* __restrict__ b1) {
    const int di   = blockIdx.x * 8 + (threadIdx.x >> 5);
    const int lane = threadIdx.x & 31;
    if (di >= NN) return;
    const int beg = g_rs[di], end = g_rs[di + 1];
    const int h8  = lane >> 3;                  // head of this lane's features

    float ax = 0.f, ay = 0.f, az = 0.f, aw = 0.f, den = 0.f;

    for (int p0 = beg; p0 < end; p0 += 32) {
        const int m  = min(32, end - p0);
        const int sl = (p0 + lane < end) ? g_es[p0 + lane] : 0;
        const int nc = (m + 7) >> 3;
        for (int c = 0; c < nc; c++) {
            const int base = c * 8;
            const float wv = g_ew4[(size_t)(p0 + base) * 4 + lane];  // 8 edges × 4 heads
            const int mm = m - base;
            if (mm >= 8) {
                #pragma unroll
                for (int j = 0; j < 8; j++) {
                    const int   si = __shfl_sync(FULL, sl, base + j);
                    const float w  = __shfl_sync(FULL, wv, j * 4 + h8);
                    const float4 hl = *(const float4*)&g_h1[(size_t)si * F1 + lane * 4];
                    ax += w * hl.x; ay += w * hl.y; az += w * hl.z; aw += w * hl.w;
                    den += w;
                }
            } else {
                for (int j = 0; j < mm; j++) {
                    const int   si = __shfl_sync(FULL, sl, base + j);
                    const float w  = __shfl_sync(FULL, wv, j * 4 + h8);
                    const float4 hl = *(const float4*)&g_h1[(size_t)si * F1 + lane * 4];
                    ax += w * hl.x; ay += w * hl.y; az += w * hl.z; aw += w * hl.w;
                    den += w;
                }
            }
        }
    }
    const float4 bb = *(const float4*)&b1[lane * 4];
    const float inv = 1.f / den;
    float4 o;
    o.x = fmaxf(ax * inv + bb.x, 0.f);
    o.y = fmaxf(ay * inv + bb.y, 0.f);
    o.z = fmaxf(az * inv + bb.z, 0.f);
    o.w = fmaxf(aw * inv + bb.w, 0.f);
    *(float4*)&g_x2[(size_t)di * F1 + lane * 4] = o;
}

// ---------------- K4: h2 = x2 @ W2 + attention dots ----------------------
__global__ void k4_gemm2(const float* __restrict__ W2,
                         const float* __restrict__ as2,
                         const float* __restrict__ ad2) {
    __shared__ float xs[32 * FIN];
    const int n0  = blockIdx.x * 32;
    const int tid = threadIdx.x;
    const float4* src4 = (const float4*)&g_x2[(size_t)n0 * FIN];
    float4* xs4 = (float4*)xs;
    #pragma unroll
    for (int it = 0; it < 4; it++)
        xs4[tid + it * 256] = src4[tid + it * 256];   // padded g_x2: safe
    __syncthreads();

    const int lane = tid & 31, w = tid >> 5;   // lane = output col c
    const float4* x0 = (const float4*)&xs[(w * 4 + 0) * FIN];
    const float4* x1 = (const float4*)&xs[(w * 4 + 1) * FIN];
    const float4* x2 = (const float4*)&xs[(w * 4 + 2) * FIN];
    const float4* x3 = (const float4*)&xs[(w * 4 + 3) * FIN];
    float acc[4] = {0.f, 0.f, 0.f, 0.f};
    #pragma unroll 8
    for (int k4i = 0; k4i < FIN / 4; k4i++) {
        const float wt0 = W2[(k4i * 4 + 0) * HID + lane];
        const float wt1 = W2[(k4i * 4 + 1) * HID + lane];
        const float wt2 = W2[(k4i * 4 + 2) * HID + lane];
        const float wt3 = W2[(k4i * 4 + 3) * HID + lane];
        const float4 a = x0[k4i], b = x1[k4i], c = x2[k4i], d = x3[k4i];
        acc[0] += a.x * wt0 + a.y * wt1 + a.z * wt2 + a.w * wt3;
        acc[1] += b.x * wt0 + b.y * wt1 + b.z * wt2 + b.w * wt3;
        acc[2] += c.x * wt0 + c.y * wt1 + c.z * wt2 + c.w * wt3;
        acc[3] += d.x * wt0 + d.y * wt1 + d.z * wt2 + d.w * wt3;
    }
    const float a_s = as2[lane], a_d = ad2[lane];
    #pragma unroll
    for (int j = 0; j < 4; j++) {
        const int n = n0 + w * 4 + j;
        if (n >= NN) break;
        g_h2[n * HID + lane] = acc[j];
        float s = acc[j] * a_s;
        float d = acc[j] * a_d;
        #pragma unroll
        for (int o = 16; o > 0; o >>= 1) {
            s += __shfl_down_sync(FULL, s, o);
            d += __shfl_down_sync(FULL, d, o);
        }
        if (lane == 0) { g_as2[n] = s; g_ad2[n] = d; }
    }
}

// ---------------- K_W2: layer-2 edge weights ----------------
__global__ void k_w2() {
    const int t = blockIdx.x * blockDim.x + threadIdx.x;
    if (t >= ET) return;
    g_ew2[t] = __expf(lrelu(g_as2[g_es[t]] + g_ad2[g_ed[t]]));
}

// ---------------- K_AGG2: gather layer 2 + relu + mean-pool --------------
__global__ void k_agg2(const int* __restrict__ batch, const float* __restrict__ b2) {
    const int di   = blockIdx.x * 8 + (threadIdx.x >> 5);
    const int lane = threadIdx.x & 31;
    if (di >= NN) return;
    const int beg = g_rs[di], end = g_rs[di + 1];

    float a0 = 0.f, a1 = 0.f, a2 = 0.f, a3 = 0.f, den = 0.f;
    for (int p0 = beg; p0 < end; p0 += 32) {
        const int  m     = min(32, end - p0);
        const bool valid = (p0 + lane < end);
        const int   sl = valid ? g_es [p0 + lane] : 0;
        const float wl = valid ? g_ew2[p0 + lane] : 0.f;
        int j = 0;
        for (; j + 4 <= m; j += 4) {
            const int   s0 = __shfl_sync(FULL, sl, j);
            const int   s1 = __shfl_sync(FULL, sl, j + 1);
            const int   s2 = __shfl_sync(FULL, sl, j + 2);
            const int   s3 = __shfl_sync(FULL, sl, j + 3);
            const float w0 = __shfl_sync(FULL, wl, j);
            const float w1 = __shfl_sync(FULL, wl, j + 1);
            const float w2 = __shfl_sync(FULL, wl, j + 2);
            const float w3 = __shfl_sync(FULL, wl, j + 3);
            a0 += w0 * g_h2[s0 * HID + lane];
            a1 += w1 * g_h2[s1 * HID + lane];
            a2 += w2 * g_h2[s2 * HID + lane];
            a3 += w3 * g_h2[s3 * HID + lane];
            den += (w0 + w1) + (w2 + w3);
        }
        for (; j < m; j++) {
            const int   s0 = __shfl_sync(FULL, sl, j);
            const float w0 = __shfl_sync(FULL, wl, j);
            a0 += w0 * g_h2[s0 * HID + lane];
            den += w0;
        }
    }
    const float acc = (a0 + a1) + (a2 + a3);
    const float v = fmaxf(acc / den + b2[lane], 0.f);
    const int g = batch[di];
    atomicAdd(&g_psum[g * HID + lane], v);
    if (lane == 0) atomicAdd(&g_cnt[g], 1.f);
}

// ---------------- K8: final FC ----------------
__global__ void k8_fc(const float* __restrict__ fcw, const float* __restrict__ fcb,
                      float* __restrict__ out) {
    const int tid = threadIdx.x;
    if (tid >= GG * OUTD) return;
    const int g = tid / OUTD, o = tid % OUTD;
    const float inv = 1.f / fmaxf(g_cnt[g], 1.f);
    float acc = fcb[o];
    #pragma unroll
    for (int c = 0; c < HID; c++)
        acc += g_psum[g * HID + c] * inv * fcw[c * OUTD + o];
    out[tid] = acc;
}

// ---------------- launch ----------------
extern "C" void kernel_launch(void* const* d_in, const int* in_sizes, int n_in,
                              void* d_out, int out_size) {
    const float* x    = (const float*)d_in[0];
    const int*   esrc = (const int*)  d_in[1];
    const int*   edst = (const int*)  d_in[2];
    const int*   batch= (const int*)  d_in[3];
    const float* W1   = (const float*)d_in[4];
    const float* as1  = (const float*)d_in[5];
    const float* ad1  = (const float*)d_in[6];
    const float* b1   = (const float*)d_in[7];
    const float* W2   = (const float*)d_in[8];
    const float* as2  = (const float*)d_in[9];
    const float* ad2  = (const float*)d_in[10];
    const float* b2   = (const float*)d_in[11];
    const float* fcw  = (const float*)d_in[12];
    const float* fcb  = (const float*)d_in[13];
    float* out = (float*)d_out;

    k_init   <<<(NN + 255) / 256, 256>>>();
    k_count  <<<(EE + 255) / 256, 256>>>(edst);
    k_scan1  <<<NB, 256>>>();
    k_scan2  <<<1, 256>>>();
    k_scan3  <<<NB, 256>>>();
    k1_gemm1 <<<NN / 16, 128>>>(x, W1, as1, ad1);
    k_scatter<<<(ET + 255) / 256, 256>>>(esrc, edst);
    k_agg1   <<<(NN + 7) / 8, 256>>>(b1);
    k4_gemm2 <<<(NN + 31) / 32, 256>>>(W2, as2, ad2);
    k_w2     <<<(ET + 255) / 256, 256>>>();
    k_agg2   <<<(NN + 7) / 8, 256>>>(batch, b2);
    k8_fc    <<<1, 640>>>(fcw, fcb, out);
}

// round 7
// speedup vs baseline: 1.8032x; 1.0783x over previous
#include <cuda_runtime.h>
#include <cuda_fp16.h>

// ---------------- problem constants ----------------
#define NN    50000
#define NNP   50016         // NN padded to multiple of 32 (k4 tile reads)
#define EE    800000
#define ET    (EE + NN)     // edges + self loops
#define GG    64
#define FIN   128
#define HID   32
#define HEADS 4
#define F1    (HEADS * HID) // 128
#define OUTD  10
#define NEG   0.2f
#define FULL  0xffffffffu
#define NB    196           // scan blocks: 196*256 = 50176 >= NN

// ---------------- device scratch (no allocations allowed) ----------------
__device__ __half g_h1h[NN * F1];       // layer-1 transformed features (fp16)
__device__ float  g_as1 [NN * HEADS];
__device__ float  g_ad1 [NN * HEADS];
__device__ float  g_x2  [NNP * F1];     // relu(layer1 out + b1)  (padded)
__device__ __half g_h2h [NN * HID];     // layer-2 transformed features (fp16)
__device__ float  g_as2 [NN];
__device__ float  g_ad2 [NN];
__device__ float  g_psum[GG * HID];
__device__ float  g_cnt [GG];
// CSR-by-destination
__device__ int    g_deg   [NN];
__device__ int    g_cursor[NN];
__device__ int    g_rs    [NN + 1];
__device__ int    g_es    [ET];         // src node per CSR slot
__device__ float  g_ew4 [(ET + 8) * 4]; // layer-1 weights, 4 heads/slot (padded)
__device__ int    g_bsum[NB];
__device__ int    g_boff[NB];

__device__ __forceinline__ float lrelu(float v) { return v > 0.f ? v : NEG * v; }

// ---------------- K0: init counters + pooled accumulators ----------------
__global__ void k_init() {
    const int i = blockIdx.x * blockDim.x + threadIdx.x;
    if (i < NN) g_deg[i] = 1;          // 1 = self loop
    if (i < GG * HID) g_psum[i] = 0.f;
    if (i < GG) g_cnt[i] = 0.f;
}

// ---------------- K0b: count in-degree ----------------
__global__ void k_count(const int* __restrict__ dst) {
    const int e = blockIdx.x * blockDim.x + threadIdx.x;
    if (e < EE) atomicAdd(&g_deg[dst[e]], 1);
}

// ---------------- scan 1: per-block sums ----------------
__global__ void k_scan1() {
    __shared__ int ws[8];
    const int tid = threadIdx.x, lane = tid & 31, wid = tid >> 5;
    const int i = blockIdx.x * 256 + tid;
    int s = (i < NN) ? g_deg[i] : 0;
    #pragma unroll
    for (int o = 16; o; o >>= 1) s += __shfl_down_sync(FULL, s, o);
    if (lane == 0) ws[wid] = s;
    __syncthreads();
    if (wid == 0) {
        int t = (lane < 8) ? ws[lane] : 0;
        #pragma unroll
        for (int o = 4; o; o >>= 1) t += __shfl_down_sync(FULL, t, o);
        if (lane == 0) g_bsum[blockIdx.x] = t;
    }
}

// ---------------- scan 2: exclusive scan of block sums (1 block) ---------
__global__ void k_scan2() {
    __shared__ int ws[8];
    const int tid = threadIdx.x, lane = tid & 31, wid = tid >> 5;
    const int v = (tid < NB) ? g_bsum[tid] : 0;
    int s = v;
    #pragma unroll
    for (int o = 1; o < 32; o <<= 1) {
        const int t = __shfl_up_sync(FULL, s, o);
        if (lane >= o) s += t;
    }
    if (lane == 31) ws[wid] = s;
    __syncthreads();
    if (wid == 0) {
        int t = (lane < 8) ? ws[lane] : 0;
        #pragma unroll
        for (int o = 1; o < 8; o <<= 1) {
            const int u = __shfl_up_sync(FULL, t, o);
            if (lane >= o) t += u;
        }
        if (lane < 8) ws[lane] = t;
    }
    __syncthreads();
    const int base = wid ? ws[wid - 1] : 0;
    if (tid < NB) g_boff[tid] = base + s - v;   // exclusive
}

// ---------------- scan 3: block prefix + rs + cursor ----------------
__global__ void k_scan3() {
    __shared__ int ws[8];
    const int tid = threadIdx.x, lane = tid & 31, wid = tid >> 5;
    const int i = blockIdx.x * 256 + tid;
    const int v = (i < NN) ? g_deg[i] : 0;
    int s = v;
    #pragma unroll
    for (int o = 1; o < 32; o <<= 1) {
        const int t = __shfl_up_sync(FULL, s, o);
        if (lane >= o) s += t;
    }
    if (lane == 31) ws[wid] = s;
    __syncthreads();
    if (wid == 0) {
        int t = (lane < 8) ? ws[lane] : 0;
        #pragma unroll
        for (int o = 1; o < 8; o <<= 1) {
            const int u = __shfl_up_sync(FULL, t, o);
            if (lane >= o) t += u;
        }
        if (lane < 8) ws[lane] = t;
    }
    __syncthreads();
    const int incl = (wid ? ws[wid - 1] : 0) + s + g_boff[blockIdx.x];
    if (i < NN) { g_rs[i + 1] = incl; g_cursor[i] = incl - v; }
    if (i == 0) g_rs[0] = 0;
}

// ---------------- K1: h1 = x @ W1 + attention dots (32 nodes/block) ------
// smem row stride 36 floats: float4-aligned (144B), stores 4-way conflicted max.
#define XS_STR 36
__global__ void k1_gemm1(const float* __restrict__ x,
                         const float* __restrict__ W1,
                         const float* __restrict__ as1,
                         const float* __restrict__ ad1) {
    __shared__ float xs[FIN * XS_STR];
    const int n0  = blockIdx.x * 32;
    const int tid = threadIdx.x;           // = output column j (0..127)
    #pragma unroll 4
    for (int i = 0; i < 32; i++) {
        const int n = n0 + i;
        xs[tid * XS_STR + i] = (n < NN) ? x[(size_t)n * FIN + tid] : 0.f;
    }
    __syncthreads();

    float acc[32];
    #pragma unroll
    for (int i = 0; i < 32; i++) acc[i] = 0.f;

    for (int k = 0; k < FIN; k++) {
        const float w = W1[k * F1 + tid];
        const float4* xr = (const float4*)&xs[k * XS_STR];
        #pragma unroll
        for (int q = 0; q < 8; q++) {
            const float4 a = xr[q];             // broadcast LDS
            acc[q * 4 + 0] += a.x * w;
            acc[q * 4 + 1] += a.y * w;
            acc[q * 4 + 2] += a.z * w;
            acc[q * 4 + 3] += a.w * w;
        }
    }

    const int lane = tid & 31, wid = tid >> 5;  // wid == head
    const float a_s = as1[tid], a_d = ad1[tid];
    #pragma unroll
    for (int i = 0; i < 32; i++) {
        const int n = n0 + i;
        if (n >= NN) break;
        g_h1h[(size_t)n * F1 + tid] = __float2half(acc[i]);
        float s = acc[i] * a_s;
        float d = acc[i] * a_d;
        #pragma unroll
        for (int o = 16; o > 0; o >>= 1) {
            s += __shfl_down_sync(FULL, s, o);
            d += __shfl_down_sync(FULL, d, o);
        }
        if (lane == 0) {
            g_as1[n * HEADS + wid] = s;
            g_ad1[n * HEADS + wid] = d;
        }
    }
}

// ---------------- K_SCAT: scatter into CSR + layer-1 edge weights --------
__global__ void k_scatter(const int* __restrict__ src, const int* __restrict__ dst) {
    const int e = blockIdx.x * blockDim.x + threadIdx.x;
    if (e >= ET) return;
    int si, di;
    if (e < EE) { si = src[e]; di = dst[e]; }
    else        { si = di = e - EE; }
    const int slot = atomicAdd(&g_cursor[di], 1);
    g_es[slot] = si;
    const float4 s4 = ((const float4*)g_as1)[si];
    const float4 d4 = ((const float4*)g_ad1)[di];
    float4 w;
    w.x = __expf(lrelu(s4.x + d4.x));
    w.y = __expf(lrelu(s4.y + d4.y));
    w.z = __expf(lrelu(s4.z + d4.z));
    w.w = __expf(lrelu(s4.w + d4.w));
    ((float4*)g_ew4)[slot] = w;
}

// ---------------- K_AGG1: gather layer 1, warp per dst, 4 fp16 feats/lane -
__global__ void k_agg1(const float* __restrict__ b1) {
    const int di   = blockIdx.x * 8 + (threadIdx.x >> 5);
    const int lane = threadIdx.x & 31;
    if (di >= NN) return;
    const int beg = g_rs[di], end = g_rs[di + 1];
    const int h8  = lane >> 3;                  // head of this lane's features

    float ax = 0.f, ay = 0.f, az = 0.f, aw = 0.f, den = 0.f;

    for (int p0 = beg; p0 < end; p0 += 32) {
        const int m  = min(32, end - p0);
        const int sl = (p0 + lane < end) ? g_es[p0 + lane] : 0;
        const int nc = (m + 7) >> 3;
        for (int c = 0; c < nc; c++) {
            const int base = c * 8;
            const float wv = g_ew4[(size_t)(p0 + base) * 4 + lane];  // 8 edges × 4 heads
            const int mm = m - base;
            if (mm >= 8) {
                #pragma unroll
                for (int j = 0; j < 8; j++) {
                    const int   si = __shfl_sync(FULL, sl, base + j);
                    const float w  = __shfl_sync(FULL, wv, j * 4 + h8);
                    const uint2 u  = *(const uint2*)&g_h1h[(size_t)si * F1 + lane * 4];
                    const float2 f0 = __half22float2(*(const __half2*)&u.x);
                    const float2 f1 = __half22float2(*(const __half2*)&u.y);
                    ax += w * f0.x; ay += w * f0.y; az += w * f1.x; aw += w * f1.y;
                    den += w;
                }
            } else {
                for (int j = 0; j < mm; j++) {
                    const int   si = __shfl_sync(FULL, sl, base + j);
                    const float w  = __shfl_sync(FULL, wv, j * 4 + h8);
                    const uint2 u  = *(const uint2*)&g_h1h[(size_t)si * F1 + lane * 4];
                    const float2 f0 = __half22float2(*(const __half2*)&u.x);
                    const float2 f1 = __half22float2(*(const __half2*)&u.y);
                    ax += w * f0.x; ay += w * f0.y; az += w * f1.x; aw += w * f1.y;
                    den += w;
                }
            }
        }
    }
    const float4 bb = *(const float4*)&b1[lane * 4];
    const float inv = 1.f / den;
    float4 o;
    o.x = fmaxf(ax * inv + bb.x, 0.f);
    o.y = fmaxf(ay * inv + bb.y, 0.f);
    o.z = fmaxf(az * inv + bb.z, 0.f);
    o.w = fmaxf(aw * inv + bb.w, 0.f);
    *(float4*)&g_x2[(size_t)di * F1 + lane * 4] = o;
}

// ---------------- K4: h2 = x2 @ W2 + attention dots ----------------------
__global__ void k4_gemm2(const float* __restrict__ W2,
                         const float* __restrict__ as2,
                         const float* __restrict__ ad2) {
    __shared__ float xs[32 * FIN];
    const int n0  = blockIdx.x * 32;
    const int tid = threadIdx.x;
    const float4* src4 = (const float4*)&g_x2[(size_t)n0 * FIN];
    float4* xs4 = (float4*)xs;
    #pragma unroll
    for (int it = 0; it < 4; it++)
        xs4[tid + it * 256] = src4[tid + it * 256];   // padded g_x2: safe
    __syncthreads();

    const int lane = tid & 31, w = tid >> 5;   // lane = output col c
    const float4* x0 = (const float4*)&xs[(w * 4 + 0) * FIN];
    const float4* x1 = (const float4*)&xs[(w * 4 + 1) * FIN];
    const float4* x2 = (const float4*)&xs[(w * 4 + 2) * FIN];
    const float4* x3 = (const float4*)&xs[(w * 4 + 3) * FIN];
    float acc[4] = {0.f, 0.f, 0.f, 0.f};
    #pragma unroll 8
    for (int k4i = 0; k4i < FIN / 4; k4i++) {
        const float wt0 = W2[(k4i * 4 + 0) * HID + lane];
        const float wt1 = W2[(k4i * 4 + 1) * HID + lane];
        const float wt2 = W2[(k4i * 4 + 2) * HID + lane];
        const float wt3 = W2[(k4i * 4 + 3) * HID + lane];
        const float4 a = x0[k4i], b = x1[k4i], c = x2[k4i], d = x3[k4i];
        acc[0] += a.x * wt0 + a.y * wt1 + a.z * wt2 + a.w * wt3;
        acc[1] += b.x * wt0 + b.y * wt1 + b.z * wt2 + b.w * wt3;
        acc[2] += c.x * wt0 + c.y * wt1 + c.z * wt2 + c.w * wt3;
        acc[3] += d.x * wt0 + d.y * wt1 + d.z * wt2 + d.w * wt3;
    }
    const float a_s = as2[lane], a_d = ad2[lane];
    #pragma unroll
    for (int j = 0; j < 4; j++) {
        const int n = n0 + w * 4 + j;
        if (n >= NN) break;
        g_h2h[n * HID + lane] = __float2half(acc[j]);
        float s = acc[j] * a_s;
        float d = acc[j] * a_d;
        #pragma unroll
        for (int o = 16; o > 0; o >>= 1) {
            s += __shfl_down_sync(FULL, s, o);
            d += __shfl_down_sync(FULL, d, o);
        }
        if (lane == 0) { g_as2[n] = s; g_ad2[n] = d; }
    }
}

// ---------------- K_AGG2: gather layer 2 (fused weights) + mean-pool -----
__global__ void k_agg2(const int* __restrict__ batch, const float* __restrict__ b2) {
    const int di   = blockIdx.x * 8 + (threadIdx.x >> 5);
    const int lane = threadIdx.x & 31;
    if (di >= NN) return;
    const int   beg = g_rs[di], end = g_rs[di + 1];
    const float ad  = g_ad2[di];

    float a0 = 0.f, a1 = 0.f, a2 = 0.f, a3 = 0.f, den = 0.f;
    for (int p0 = beg; p0 < end; p0 += 32) {
        const int  m     = min(32, end - p0);
        const bool valid = (p0 + lane < end);
        const int   sl = valid ? g_es[p0 + lane] : 0;
        const float wl = valid ? __expf(lrelu(g_as2[sl] + ad)) : 0.f;
        int j = 0;
        for (; j + 4 <= m; j += 4) {
            const int   s0 = __shfl_sync(FULL, sl, j);
            const int   s1 = __shfl_sync(FULL, sl, j + 1);
            const int   s2 = __shfl_sync(FULL, sl, j + 2);
            const int   s3 = __shfl_sync(FULL, sl, j + 3);
            const float w0 = __shfl_sync(FULL, wl, j);
            const float w1 = __shfl_sync(FULL, wl, j + 1);
            const float w2 = __shfl_sync(FULL, wl, j + 2);
            const float w3 = __shfl_sync(FULL, wl, j + 3);
            a0 += w0 * __half2float(g_h2h[s0 * HID + lane]);
            a1 += w1 * __half2float(g_h2h[s1 * HID + lane]);
            a2 += w2 * __half2float(g_h2h[s2 * HID + lane]);
            a3 += w3 * __half2float(g_h2h[s3 * HID + lane]);
            den += (w0 + w1) + (w2 + w3);
        }
        for (; j < m; j++) {
            const int   s0 = __shfl_sync(FULL, sl, j);
            const float w0 = __shfl_sync(FULL, wl, j);
            a0 += w0 * __half2float(g_h2h[s0 * HID + lane]);
            den += w0;
        }
    }
    const float acc = (a0 + a1) + (a2 + a3);
    const float v = fmaxf(acc / den + b2[lane], 0.f);
    const int g = batch[di];
    atomicAdd(&g_psum[g * HID + lane], v);
    if (lane == 0) atomicAdd(&g_cnt[g], 1.f);
}

// ---------------- K8: final FC ----------------
__global__ void k8_fc(const float* __restrict__ fcw, const float* __restrict__ fcb,
                      float* __restrict__ out) {
    const int tid = threadIdx.x;
    if (tid >= GG * OUTD) return;
    const int g = tid / OUTD, o = tid % OUTD;
    const float inv = 1.f / fmaxf(g_cnt[g], 1.f);
    float acc = fcb[o];
    #pragma unroll
    for (int c = 0; c < HID; c++)
        acc += g_psum[g * HID + c] * inv * fcw[c * OUTD + o];
    out[tid] = acc;
}

// ---------------- launch ----------------
extern "C" void kernel_launch(void* const* d_in, const int* in_sizes, int n_in,
                              void* d_out, int out_size) {
    const float* x    = (const float*)d_in[0];
    const int*   esrc = (const int*)  d_in[1];
    const int*   edst = (const int*)  d_in[2];
    const int*   batch= (const int*)  d_in[3];
    const float* W1   = (const float*)d_in[4];
    const float* as1  = (const float*)d_in[5];
    const float* ad1  = (const float*)d_in[6];
    const float* b1   = (const float*)d_in[7];
    const float* W2   = (const float*)d_in[8];
    const float* as2  = (const float*)d_in[9];
    const float* ad2  = (const float*)d_in[10];
    const float* b2   = (const float*)d_in[11];
    const float* fcw  = (const float*)d_in[12];
    const float* fcb  = (const float*)d_in[13];
    float* out = (float*)d_out;

    k_init   <<<(NN + 255) / 256, 256>>>();
    k_count  <<<(EE + 255) / 256, 256>>>(edst);
    k_scan1  <<<NB, 256>>>();
    k_scan2  <<<1, 256>>>();
    k_scan3  <<<NB, 256>>>();
    k1_gemm1 <<<(NN + 31) / 32, 128>>>(x, W1, as1, ad1);
    k_scatter<<<(ET + 255) / 256, 256>>>(esrc, edst);
    k_agg1   <<<(NN + 7) / 8, 256>>>(b1);
    k4_gemm2 <<<(NN + 31) / 32, 256>>>(W2, as2, ad2);
    k_agg2   <<<(NN + 7) / 8, 256>>>(batch, b2);
    k8_fc    <<<1, 640>>>(fcw, fcb, out);
}

// round 8
// speedup vs baseline: 1.9486x; 1.0806x over previous
#include <cuda_runtime.h>
#include <cuda_fp16.h>

// ---------------- problem constants ----------------
#define NN    50000
#define NNP   50016         // NN padded to multiple of 32 (k4 tile reads)
#define EE    800000
#define ET    (EE + NN)     // edges + self loops
#define GG    64
#define FIN   128
#define HID   32
#define HEADS 4
#define F1    (HEADS * HID) // 128
#define OUTD  10
#define NEG   0.2f
#define FULL  0xffffffffu
#define NB    196           // scan blocks: 196*256 = 50176 >= NN

// ---------------- device scratch (no allocations allowed) ----------------
__device__ __half g_h1h[NN * F1];       // layer-1 transformed features (fp16)
__device__ float  g_as1 [NN * HEADS];
__device__ float  g_ad1 [NN * HEADS];
__device__ float  g_x2  [NNP * F1];     // relu(layer1 out + b1)  (padded)
__device__ __half g_h2h [NN * HID];     // layer-2 transformed features (fp16)
__device__ float  g_as2 [NN];
__device__ float  g_ad2 [NN];
__device__ float  g_psum[GG * HID];
__device__ float  g_cnt [GG];
// CSR-by-destination
__device__ int    g_deg   [NN];
__device__ int    g_cursor[NN];
__device__ int    g_rs    [NN + 1];
__device__ int    g_es    [ET];         // src node per CSR slot
// decoupled-lookback scan state
__device__ unsigned long long g_stat[NB];
__device__ int    g_tilectr;

__device__ __forceinline__ float lrelu(float v) { return v > 0.f ? v : NEG * v; }

// ---------------- K0: init counters + pooled accumulators + scan state ---
__global__ void k_init() {
    const int i = blockIdx.x * blockDim.x + threadIdx.x;
    if (i < NN) g_deg[i] = 1;          // 1 = self loop
    if (i < GG * HID) g_psum[i] = 0.f;
    if (i < GG) g_cnt[i] = 0.f;
    if (i < NB) g_stat[i] = 0ull;
    if (i == 0) g_tilectr = 0;
}

// ---------------- K0b: count in-degree ----------------
__global__ void k_count(const int* __restrict__ dst) {
    const int e = blockIdx.x * blockDim.x + threadIdx.x;
    if (e < EE) atomicAdd(&g_deg[dst[e]], 1);
}

// ---------------- scan: single-kernel decoupled lookback -----------------
__global__ void k_scan() {
    __shared__ int sbid;
    __shared__ int ws[8];
    __shared__ int s_prefix;
    const int tid = threadIdx.x, lane = tid & 31, wid = tid >> 5;
    if (tid == 0) sbid = atomicAdd(&g_tilectr, 1);
    __syncthreads();
    const int bid = sbid;
    const int i   = bid * 256 + tid;
    const int v   = (i < NN) ? g_deg[i] : 0;

    // block-wide inclusive scan of v
    int s = v;
    #pragma unroll
    for (int o = 1; o < 32; o <<= 1) {
        const int t = __shfl_up_sync(FULL, s, o);
        if (lane >= o) s += t;
    }
    if (lane == 31) ws[wid] = s;
    __syncthreads();
    if (wid == 0) {
        int t = (lane < 8) ? ws[lane] : 0;
        #pragma unroll
        for (int o = 1; o < 8; o <<= 1) {
            const int u = __shfl_up_sync(FULL, t, o);
            if (lane >= o) t += u;
        }
        if (lane < 8) ws[lane] = t;
    }
    __syncthreads();
    const int incl  = (wid ? ws[wid - 1] : 0) + s;   // inclusive within block
    const int total = ws[7];

    if (tid == 0) {
        if (bid > 0)   // publish aggregate first (flag=1)
            atomicExch(&g_stat[bid], (1ull << 32) | (unsigned int)total);
        int prefix = 0;
        if (bid > 0) {
            int k = bid - 1;
            while (true) {
                unsigned long long st;
                do { st = *(volatile unsigned long long*)&g_stat[k]; }
                while ((st >> 32) == 0ull);
                prefix += (int)(unsigned int)(st & 0xffffffffull);
                if ((st >> 32) == 2ull) break;
                k--;
            }
        }
        s_prefix = prefix;
        atomicExch(&g_stat[bid], (2ull << 32) | (unsigned int)(prefix + total));
    }
    __syncthreads();
    const int base = s_prefix;
    if (i < NN) {
        g_rs[i + 1]  = base + incl;
        g_cursor[i]  = base + incl - v;
    }
    if (i == 0) g_rs[0] = 0;
}

// ---------------- K_SCAT: pure CSR permutation ----------------
__global__ void k_scatter(const int* __restrict__ src, const int* __restrict__ dst) {
    const int e = blockIdx.x * blockDim.x + threadIdx.x;
    if (e >= ET) return;
    int si, di;
    if (e < EE) { si = src[e]; di = dst[e]; }
    else        { si = di = e - EE; }
    g_es[atomicAdd(&g_cursor[di], 1)] = si;
}

// ---------------- K1: h1 = x @ W1 + attention dots (32 nodes/block) ------
#define XS_STR 36
__global__ void k1_gemm1(const float* __restrict__ x,
                         const float* __restrict__ W1,
                         const float* __restrict__ as1,
                         const float* __restrict__ ad1) {
    __shared__ float xs[FIN * XS_STR];
    const int n0  = blockIdx.x * 32;
    const int tid = threadIdx.x;           // = output column j (0..127)
    #pragma unroll 4
    for (int i = 0; i < 32; i++) {
        const int n = n0 + i;
        xs[tid * XS_STR + i] = (n < NN) ? x[(size_t)n * FIN + tid] : 0.f;
    }
    __syncthreads();

    float acc[32];
    #pragma unroll
    for (int i = 0; i < 32; i++) acc[i] = 0.f;

    for (int k = 0; k < FIN; k++) {
        const float w = W1[k * F1 + tid];
        const float4* xr = (const float4*)&xs[k * XS_STR];
        #pragma unroll
        for (int q = 0; q < 8; q++) {
            const float4 a = xr[q];             // broadcast LDS
            acc[q * 4 + 0] += a.x * w;
            acc[q * 4 + 1] += a.y * w;
            acc[q * 4 + 2] += a.z * w;
            acc[q * 4 + 3] += a.w * w;
        }
    }

    const int lane = tid & 31, wid = tid >> 5;  // wid == head
    const float a_s = as1[tid], a_d = ad1[tid];
    #pragma unroll
    for (int i = 0; i < 32; i++) {
        const int n = n0 + i;
        if (n >= NN) break;
        g_h1h[(size_t)n * F1 + tid] = __float2half(acc[i]);
        float s = acc[i] * a_s;
        float d = acc[i] * a_d;
        #pragma unroll
        for (int o = 16; o > 0; o >>= 1) {
            s += __shfl_down_sync(FULL, s, o);
            d += __shfl_down_sync(FULL, d, o);
        }
        if (lane == 0) {
            g_as1[n * HEADS + wid] = s;
            g_ad1[n * HEADS + wid] = d;
        }
    }
}

// ---------------- K_AGG1: gather layer 1, in-register edge weights -------
// lane layout per 8-edge chunk: lane = (edge-base)*4 + head
__global__ void k_agg1(const float* __restrict__ b1) {
    const int di   = blockIdx.x * 8 + (threadIdx.x >> 5);
    const int lane = threadIdx.x & 31;
    if (di >= NN) return;
    const int beg = g_rs[di], end = g_rs[di + 1];
    const int h8   = lane >> 3;                 // head of this lane's output feats
    const int hsel = lane & 3;                  // head this lane computes weights for
    const int esel = lane >> 2;                 // chunk-local edge index for weights
    const float adv = g_ad1[di * 4 + hsel];

    float ax = 0.f, ay = 0.f, az = 0.f, aw = 0.f, den = 0.f;

    for (int p0 = beg; p0 < end; p0 += 32) {
        const int m  = min(32, end - p0);
        const int sl = (p0 + lane < end) ? g_es[p0 + lane] : 0;
        const int nc = (m + 7) >> 3;
        for (int c = 0; c < nc; c++) {
            const int base = c * 8;
            // per-lane weight for (edge base+esel, head hsel)
            const int  sle = __shfl_sync(FULL, sl, base + esel);
            float w = 0.f;
            if (p0 + base + esel < end)
                w = __expf(lrelu(g_as1[sle * 4 + hsel] + adv));
            den += w;
            const int mm = m - base;
            if (mm >= 8) {
                #pragma unroll
                for (int j = 0; j < 8; j++) {
                    const int   si = __shfl_sync(FULL, sl, base + j);
                    const float wj = __shfl_sync(FULL, w, j * 4 + h8);
                    const uint2 u  = *(const uint2*)&g_h1h[(size_t)si * F1 + lane * 4];
                    const float2 f0 = __half22float2(*(const __half2*)&u.x);
                    const float2 f1 = __half22float2(*(const __half2*)&u.y);
                    ax += wj * f0.x; ay += wj * f0.y; az += wj * f1.x; aw += wj * f1.y;
                }
            } else {
                for (int j = 0; j < mm; j++) {
                    const int   si = __shfl_sync(FULL, sl, base + j);
                    const float wj = __shfl_sync(FULL, w, j * 4 + h8);
                    const uint2 u  = *(const uint2*)&g_h1h[(size_t)si * F1 + lane * 4];
                    const float2 f0 = __half22float2(*(const __half2*)&u.x);
                    const float2 f1 = __half22float2(*(const __half2*)&u.y);
                    ax += wj * f0.x; ay += wj * f0.y; az += wj * f1.x; aw += wj * f1.y;
                }
            }
        }
    }
    // den: sum over lanes with same hsel (strides 4,8,16), then pick head h8
    den += __shfl_xor_sync(FULL, den, 4);
    den += __shfl_xor_sync(FULL, den, 8);
    den += __shfl_xor_sync(FULL, den, 16);
    const float denF = __shfl_sync(FULL, den, h8);   // lanes 0..3 hold heads 0..3

    const float4 bb = *(const float4*)&b1[lane * 4];
    const float inv = 1.f / denF;
    float4 o;
    o.x = fmaxf(ax * inv + bb.x, 0.f);
    o.y = fmaxf(ay * inv + bb.y, 0.f);
    o.z = fmaxf(az * inv + bb.z, 0.f);
    o.w = fmaxf(aw * inv + bb.w, 0.f);
    *(float4*)&g_x2[(size_t)di * F1 + lane * 4] = o;
}

// ---------------- K4: h2 = x2 @ W2 + attention dots ----------------------
__global__ void k4_gemm2(const float* __restrict__ W2,
                         const float* __restrict__ as2,
                         const float* __restrict__ ad2) {
    __shared__ float xs[32 * FIN];
    const int n0  = blockIdx.x * 32;
    const int tid = threadIdx.x;
    const float4* src4 = (const float4*)&g_x2[(size_t)n0 * FIN];
    float4* xs4 = (float4*)xs;
    #pragma unroll
    for (int it = 0; it < 4; it++)
        xs4[tid + it * 256] = src4[tid + it * 256];   // padded g_x2: safe
    __syncthreads();

    const int lane = tid & 31, w = tid >> 5;   // lane = output col c
    const float4* x0 = (const float4*)&xs[(w * 4 + 0) * FIN];
    const float4* x1 = (const float4*)&xs[(w * 4 + 1) * FIN];
    const float4* x2 = (const float4*)&xs[(w * 4 + 2) * FIN];
    const float4* x3 = (const float4*)&xs[(w * 4 + 3) * FIN];
    float acc[4] = {0.f, 0.f, 0.f, 0.f};
    #pragma unroll 8
    for (int k4i = 0; k4i < FIN / 4; k4i++) {
        const float wt0 = W2[(k4i * 4 + 0) * HID + lane];
        const float wt1 = W2[(k4i * 4 + 1) * HID + lane];
        const float wt2 = W2[(k4i * 4 + 2) * HID + lane];
        const float wt3 = W2[(k4i * 4 + 3) * HID + lane];
        const float4 a = x0[k4i], b = x1[k4i], c = x2[k4i], d = x3[k4i];
        acc[0] += a.x * wt0 + a.y * wt1 + a.z * wt2 + a.w * wt3;
        acc[1] += b.x * wt0 + b.y * wt1 + b.z * wt2 + b.w * wt3;
        acc[2] += c.x * wt0 + c.y * wt1 + c.z * wt2 + c.w * wt3;
        acc[3] += d.x * wt0 + d.y * wt1 + d.z * wt2 + d.w * wt3;
    }
    const float a_s = as2[lane], a_d = ad2[lane];
    #pragma unroll
    for (int j = 0; j < 4; j++) {
        const int n = n0 + w * 4 + j;
        if (n >= NN) break;
        g_h2h[n * HID + lane] = __float2half(acc[j]);
        float s = acc[j] * a_s;
        float d = acc[j] * a_d;
        #pragma unroll
        for (int o = 16; o > 0; o >>= 1) {
            s += __shfl_down_sync(FULL, s, o);
            d += __shfl_down_sync(FULL, d, o);
        }
        if (lane == 0) { g_as2[n] = s; g_ad2[n] = d; }
    }
}

// ---------------- K_AGG2: gather layer 2 (fused weights) + mean-pool -----
__global__ void k_agg2(const int* __restrict__ batch, const float* __restrict__ b2) {
    const int di   = blockIdx.x * 8 + (threadIdx.x >> 5);
    const int lane = threadIdx.x & 31;
    if (di >= NN) return;
    const int   beg = g_rs[di], end = g_rs[di + 1];
    const float ad  = g_ad2[di];

    float a0 = 0.f, a1 = 0.f, a2 = 0.f, a3 = 0.f, den = 0.f;
    for (int p0 = beg; p0 < end; p0 += 32) {
        const int  m     = min(32, end - p0);
        const bool valid = (p0 + lane < end);
        const int   sl = valid ? g_es[p0 + lane] : 0;
        const float wl = valid ? __expf(lrelu(g_as2[sl] + ad)) : 0.f;
        int j = 0;
        for (; j + 4 <= m; j += 4) {
            const int   s0 = __shfl_sync(FULL, sl, j);
            const int   s1 = __shfl_sync(FULL, sl, j + 1);
            const int   s2 = __shfl_sync(FULL, sl, j + 2);
            const int   s3 = __shfl_sync(FULL, sl, j + 3);
            const float w0 = __shfl_sync(FULL, wl, j);
            const float w1 = __shfl_sync(FULL, wl, j + 1);
            const float w2 = __shfl_sync(FULL, wl, j + 2);
            const float w3 = __shfl_sync(FULL, wl, j + 3);
            a0 += w0 * __half2float(g_h2h[s0 * HID + lane]);
            a1 += w1 * __half2float(g_h2h[s1 * HID + lane]);
            a2 += w2 * __half2float(g_h2h[s2 * HID + lane]);
            a3 += w3 * __half2float(g_h2h[s3 * HID + lane]);
            den += (w0 + w1) + (w2 + w3);
        }
        for (; j < m; j++) {
            const int   s0 = __shfl_sync(FULL, sl, j);
            const float w0 = __shfl_sync(FULL, wl, j);
            a0 += w0 * __half2float(g_h2h[s0 * HID + lane]);
            den += w0;
        }
    }
    const float acc = (a0 + a1) + (a2 + a3);
    const float v = fmaxf(acc / den + b2[lane], 0.f);
    const int g = batch[di];
    atomicAdd(&g_psum[g * HID + lane], v);
    if (lane == 0) atomicAdd(&g_cnt[g], 1.f);
}

// ---------------- K8: final FC ----------------
__global__ void k8_fc(const float* __restrict__ fcw, const float* __restrict__ fcb,
                      float* __restrict__ out) {
    const int tid = threadIdx.x;
    if (tid >= GG * OUTD) return;
    const int g = tid / OUTD, o = tid % OUTD;
    const float inv = 1.f / fmaxf(g_cnt[g], 1.f);
    float acc = fcb[o];
    #pragma unroll
    for (int c = 0; c < HID; c++)
        acc += g_psum[g * HID + c] * inv * fcw[c * OUTD + o];
    out[tid] = acc;
}

// ---------------- launch ----------------
extern "C" void kernel_launch(void* const* d_in, const int* in_sizes, int n_in,
                              void* d_out, int out_size) {
    const float* x    = (const float*)d_in[0];
    const int*   esrc = (const int*)  d_in[1];
    const int*   edst = (const int*)  d_in[2];
    const int*   batch= (const int*)  d_in[3];
    const float* W1   = (const float*)d_in[4];
    const float* as1  = (const float*)d_in[5];
    const float* ad1  = (const float*)d_in[6];
    const float* b1   = (const float*)d_in[7];
    const float* W2   = (const float*)d_in[8];
    const float* as2  = (const float*)d_in[9];
    const float* ad2  = (const float*)d_in[10];
    const float* b2   = (const float*)d_in[11];
    const float* fcw  = (const float*)d_in[12];
    const float* fcb  = (const float*)d_in[13];
    float* out = (float*)d_out;

    // one-time host resources (not device memory; identical launch DAG every call)
    static cudaStream_t s_csr = nullptr;
    static cudaEvent_t  ev_fork = nullptr, ev_join = nullptr;
    if (s_csr == nullptr) {
        cudaStreamCreateWithFlags(&s_csr, cudaStreamNonBlocking);
        cudaEventCreateWithFlags(&ev_fork, cudaEventDisableTiming);
        cudaEventCreateWithFlags(&ev_join, cudaEventDisableTiming);
    }

    // fork: CSR chain on s_csr, feature GEMM on default stream
    cudaEventRecord(ev_fork, 0);
    cudaStreamWaitEvent(s_csr, ev_fork, 0);

    k_init   <<<(NN + 255) / 256, 256, 0, s_csr>>>();
    k_count  <<<(EE + 255) / 256, 256, 0, s_csr>>>(edst);
    k_scan   <<<NB, 256, 0, s_csr>>>();
    k_scatter<<<(ET + 255) / 256, 256, 0, s_csr>>>(esrc, edst);
    cudaEventRecord(ev_join, s_csr);

    k1_gemm1 <<<(NN + 31) / 32, 128>>>(x, W1, as1, ad1);

    // join: aggregation needs both CSR and h1/as1
    cudaStreamWaitEvent(0, ev_join, 0);

    k_agg1   <<<(NN + 7) / 8, 256>>>(b1);
    k4_gemm2 <<<(NN + 31) / 32, 256>>>(W2, as2, ad2);
    k_agg2   <<<(NN + 7) / 8, 256>>>(batch, b2);
    k8_fc    <<<1, 640>>>(fcw, fcb, out);
}

// round 13
// speedup vs baseline: 1.9496x; 1.0006x over previous
#include <cuda_runtime.h>
#include <cuda_fp16.h>
#include <cstdint>

// ---------------- problem constants ----------------
#define NN    50000
#define NNP   50016         // NN padded to multiple of 32 (k4 tile reads)
#define EE    800000
#define ET    (EE + NN)     // edges + self loops
#define GG    64
#define FIN   128
#define HID   32
#define HEADS 4
#define F1    (HEADS * HID) // 128
#define OUTD  10
#define NEG   0.2f
#define FULL  0xffffffffu
#define NB    196           // scan blocks: 196*256 = 50176 >= NN

// ---------------- device scratch (no allocations; zero-initialized at load) --
__device__ __half g_h1h[NN * F1];       // layer-1 transformed features (fp16)
__device__ float  g_as1 [NN * HEADS];
__device__ float  g_ad1 [NN * HEADS];
__device__ float  g_x2  [NNP * F1];     // relu(layer1 out + b1)  (padded)
__device__ __half g_h2h [NN * HID];     // layer-2 transformed features (fp16)
__device__ float  g_as2 [NN];
__device__ float  g_ad2 [NN];
__device__ float  g_psum[GG * HID];     // zero at load; re-zeroed by k_cleanup
__device__ float  g_cnt [GG];
// CSR-by-destination
__device__ int    g_deg   [NN];         // zero at load; re-zeroed by k_cleanup
__device__ int    g_cursor[NN];
__device__ int    g_rs    [NN + 1];
__device__ int    g_es    [ET];         // src node per CSR slot
// decoupled-lookback scan state
__device__ unsigned long long g_stat[NB];
__device__ int    g_tilectr;
// mma probe output (diagnostic)
__device__ float  g_probe[8];

__device__ __forceinline__ float lrelu(float v) { return v > 0.f ? v : NEG * v; }

// ---------------- K_PROBE: single mma.sync on constants (diagnostic) -----
__global__ void k_probe() {
    const uint32_t one2 = 0x3c003c00u;   // half2(1,1)
    float c0 = 0.f, c1 = 0.f, c2 = 0.f, c3 = 0.f;
    asm volatile(
        "mma.sync.aligned.m16n8k16.row.col.f32.f16.f16.f32 "
        "{%0,%1,%2,%3}, {%4,%5,%6,%7}, {%8,%9}, {%0,%1,%2,%3};\n"
        : "+f"(c0), "+f"(c1), "+f"(c2), "+f"(c3)
        : "r"(one2), "r"(one2), "r"(one2), "r"(one2), "r"(one2), "r"(one2));
    if (threadIdx.x == 0) {
        g_probe[0] = c0; g_probe[1] = c1; g_probe[2] = c2; g_probe[3] = c3;
    }
}

// ---------------- K0b: count in-degree (deg starts zeroed) ----------------
__global__ void k_count(const int* __restrict__ dst) {
    const int e = blockIdx.x * blockDim.x + threadIdx.x;
    if (e < EE) atomicAdd(&g_deg[dst[e]], 1);
}

// ---------------- scan: single-kernel decoupled lookback -----------------
// v = deg[i] + 1 accounts for the self-loop (deg holds only counted edges).
__global__ void k_scan() {
    __shared__ int sbid;
    __shared__ int ws[8];
    __shared__ int s_prefix;
    const int tid = threadIdx.x, lane = tid & 31, wid = tid >> 5;
    if (tid == 0) sbid = atomicAdd(&g_tilectr, 1);
    __syncthreads();
    const int bid = sbid;
    const int i   = bid * 256 + tid;
    const int v   = (i < NN) ? (g_deg[i] + 1) : 0;

    int s = v;
    #pragma unroll
    for (int o = 1; o < 32; o <<= 1) {
        const int t = __shfl_up_sync(FULL, s, o);
        if (lane >= o) s += t;
    }
    if (lane == 31) ws[wid] = s;
    __syncthreads();
    if (wid == 0) {
        int t = (lane < 8) ? ws[lane] : 0;
        #pragma unroll
        for (int o = 1; o < 8; o <<= 1) {
            const int u = __shfl_up_sync(FULL, t, o);
            if (lane >= o) t += u;
        }
        if (lane < 8) ws[lane] = t;
    }
    __syncthreads();
    const int incl  = (wid ? ws[wid - 1] : 0) + s;
    const int total = ws[7];

    if (tid == 0) {
        if (bid > 0)
            atomicExch(&g_stat[bid], (1ull << 32) | (unsigned int)total);
        int prefix = 0;
        if (bid > 0) {
            int k = bid - 1;
            while (true) {
                unsigned long long st;
                do { st = *(volatile unsigned long long*)&g_stat[k]; }
                while ((st >> 32) == 0ull);
                prefix += (int)(unsigned int)(st & 0xffffffffull);
                if ((st >> 32) == 2ull) break;
                k--;
            }
        }
        s_prefix = prefix;
        atomicExch(&g_stat[bid], (2ull << 32) | (unsigned int)(prefix + total));
    }
    __syncthreads();
    const int base = s_prefix;
    if (i < NN) {
        g_rs[i + 1] = base + incl;
        g_cursor[i] = base + incl - v;
    }
    if (i == 0) g_rs[0] = 0;
}

// ---------------- K_SCAT: pure CSR permutation ----------------
__global__ void k_scatter(const int* __restrict__ src, const int* __restrict__ dst) {
    const int e = blockIdx.x * blockDim.x + threadIdx.x;
    if (e >= ET) return;
    int si, di;
    if (e < EE) { si = src[e]; di = dst[e]; }
    else        { si = di = e - EE; }
    g_es[atomicAdd(&g_cursor[di], 1)] = si;
}

// ---------------- K1: h1 = x @ W1 + attention dots (32 nodes/block) ------
#define XS_STR 36
__global__ void k1_gemm1(const float* __restrict__ x,
                         const float* __restrict__ W1,
                         const float* __restrict__ as1,
                         const float* __restrict__ ad1) {
    __shared__ float xs[FIN * XS_STR];
    const int n0  = blockIdx.x * 32;
    const int tid = threadIdx.x;           // = output column j (0..127)
    #pragma unroll 4
    for (int i = 0; i < 32; i++) {
        const int n = n0 + i;
        xs[tid * XS_STR + i] = (n < NN) ? x[(size_t)n * FIN + tid] : 0.f;
    }
    __syncthreads();

    float acc[32];
    #pragma unroll
    for (int i = 0; i < 32; i++) acc[i] = 0.f;

    for (int k = 0; k < FIN; k++) {
        const float w = W1[k * F1 + tid];
        const float4* xr = (const float4*)&xs[k * XS_STR];
        #pragma unroll
        for (int q = 0; q < 8; q++) {
            const float4 a = xr[q];             // broadcast LDS
            acc[q * 4 + 0] += a.x * w;
            acc[q * 4 + 1] += a.y * w;
            acc[q * 4 + 2] += a.z * w;
            acc[q * 4 + 3] += a.w * w;
        }
    }

    const int lane = tid & 31, wid = tid >> 5;  // wid == head
    const float a_s = as1[tid], a_d = ad1[tid];
    #pragma unroll
    for (int i = 0; i < 32; i++) {
        const int n = n0 + i;
        if (n >= NN) break;
        g_h1h[(size_t)n * F1 + tid] = __float2half(acc[i]);
        float s = acc[i] * a_s;
        float d = acc[i] * a_d;
        #pragma unroll
        for (int o = 16; o > 0; o >>= 1) {
            s += __shfl_down_sync(FULL, s, o);
            d += __shfl_down_sync(FULL, d, o);
        }
        if (lane == 0) {
            g_as1[n * HEADS + wid] = s;
            g_ad1[n * HEADS + wid] = d;
        }
    }
}

// ---------------- K_AGG1: gather layer 1, in-register edge weights -------
// lane layout per 8-edge chunk: lane = (edge-base)*4 + head
__global__ void k_agg1(const float* __restrict__ b1) {
    const int di   = blockIdx.x * 8 + (threadIdx.x >> 5);
    const int lane = threadIdx.x & 31;
    if (di >= NN) return;
    const int beg = g_rs[di], end = g_rs[di + 1];
    const int h8   = lane >> 3;                 // head of this lane's output feats
    const int hsel = lane & 3;                  // head this lane computes weights for
    const int esel = lane >> 2;                 // chunk-local edge index for weights
    const float adv = g_ad1[di * 4 + hsel];

    float ax = 0.f, ay = 0.f, az = 0.f, aw = 0.f, den = 0.f;

    for (int p0 = beg; p0 < end; p0 += 32) {
        const int m  = min(32, end - p0);
        const int sl = (p0 + lane < end) ? g_es[p0 + lane] : 0;
        const int nc = (m + 7) >> 3;
        for (int c = 0; c < nc; c++) {
            const int base = c * 8;
            const int  sle = __shfl_sync(FULL, sl, base + esel);
            float w = 0.f;
            if (p0 + base + esel < end)
                w = __expf(lrelu(g_as1[sle * 4 + hsel] + adv));
            den += w;
            const int mm = m - base;
            if (mm >= 8) {
                #pragma unroll
                for (int j = 0; j < 8; j++) {
                    const int   si = __shfl_sync(FULL, sl, base + j);
                    const float wj = __shfl_sync(FULL, w, j * 4 + h8);
                    const uint2 u  = *(const uint2*)&g_h1h[(size_t)si * F1 + lane * 4];
                    const float2 f0 = __half22float2(*(const __half2*)&u.x);
                    const float2 f1 = __half22float2(*(const __half2*)&u.y);
                    ax += wj * f0.x; ay += wj * f0.y; az += wj * f1.x; aw += wj * f1.y;
                }
            } else {
                for (int j = 0; j < mm; j++) {
                    const int   si = __shfl_sync(FULL, sl, base + j);
                    const float wj = __shfl_sync(FULL, w, j * 4 + h8);
                    const uint2 u  = *(const uint2*)&g_h1h[(size_t)si * F1 + lane * 4];
                    const float2 f0 = __half22float2(*(const __half2*)&u.x);
                    const float2 f1 = __half22float2(*(const __half2*)&u.y);
                    ax += wj * f0.x; ay += wj * f0.y; az += wj * f1.x; aw += wj * f1.y;
                }
            }
        }
    }
    // den: sum over lanes with same hsel (strides 4,8,16), then pick head h8
    den += __shfl_xor_sync(FULL, den, 4);
    den += __shfl_xor_sync(FULL, den, 8);
    den += __shfl_xor_sync(FULL, den, 16);
    const float denF = __shfl_sync(FULL, den, h8);   // lanes 0..3 hold heads 0..3

    const float4 bb = *(const float4*)&b1[lane * 4];
    const float inv = 1.f / denF;
    float4 o;
    o.x = fmaxf(ax * inv + bb.x, 0.f);
    o.y = fmaxf(ay * inv + bb.y, 0.f);
    o.z = fmaxf(az * inv + bb.z, 0.f);
    o.w = fmaxf(aw * inv + bb.w, 0.f);
    *(float4*)&g_x2[(size_t)di * F1 + lane * 4] = o;
}

// ---------------- K4: h2 = x2 @ W2 + attention dots ----------------------
__global__ void k4_gemm2(const float* __restrict__ W2,
                         const float* __restrict__ as2,
                         const float* __restrict__ ad2) {
    __shared__ float xs[32 * FIN];
    const int n0  = blockIdx.x * 32;
    const int tid = threadIdx.x;
    const float4* src4 = (const float4*)&g_x2[(size_t)n0 * FIN];
    float4* xs4 = (float4*)xs;
    #pragma unroll
    for (int it = 0; it < 4; it++)
        xs4[tid + it * 256] = src4[tid + it * 256];   // padded g_x2: safe
    __syncthreads();

    const int lane = tid & 31, w = tid >> 5;   // lane = output col c
    const float4* x0 = (const float4*)&xs[(w * 4 + 0) * FIN];
    const float4* x1 = (const float4*)&xs[(w * 4 + 1) * FIN];
    const float4* x2 = (const float4*)&xs[(w * 4 + 2) * FIN];
    const float4* x3 = (const float4*)&xs[(w * 4 + 3) * FIN];
    float acc[4] = {0.f, 0.f, 0.f, 0.f};
    #pragma unroll 8
    for (int k4i = 0; k4i < FIN / 4; k4i++) {
        const float wt0 = W2[(k4i * 4 + 0) * HID + lane];
        const float wt1 = W2[(k4i * 4 + 1) * HID + lane];
        const float wt2 = W2[(k4i * 4 + 2) * HID + lane];
        const float wt3 = W2[(k4i * 4 + 3) * HID + lane];
        const float4 a = x0[k4i], b = x1[k4i], c = x2[k4i], d = x3[k4i];
        acc[0] += a.x * wt0 + a.y * wt1 + a.z * wt2 + a.w * wt3;
        acc[1] += b.x * wt0 + b.y * wt1 + b.z * wt2 + b.w * wt3;
        acc[2] += c.x * wt0 + c.y * wt1 + c.z * wt2 + c.w * wt3;
        acc[3] += d.x * wt0 + d.y * wt1 + d.z * wt2 + d.w * wt3;
    }
    const float a_s = as2[lane], a_d = ad2[lane];
    #pragma unroll
    for (int j = 0; j < 4; j++) {
        const int n = n0 + w * 4 + j;
        if (n >= NN) break;
        g_h2h[n * HID + lane] = __float2half(acc[j]);
        float s = acc[j] * a_s;
        float d = acc[j] * a_d;
        #pragma unroll
        for (int o = 16; o > 0; o >>= 1) {
            s += __shfl_down_sync(FULL, s, o);
            d += __shfl_down_sync(FULL, d, o);
        }
        if (lane == 0) { g_as2[n] = s; g_ad2[n] = d; }
    }
}

// ---------------- K_AGG2: gather layer 2 (fused weights) + mean-pool -----
__global__ void k_agg2(const int* __restrict__ batch, const float* __restrict__ b2) {
    const int di   = blockIdx.x * 8 + (threadIdx.x >> 5);
    const int lane = threadIdx.x & 31;
    if (di >= NN) return;
    const int   beg = g_rs[di], end = g_rs[di + 1];
    const float ad  = g_ad2[di];

    float a0 = 0.f, a1 = 0.f, a2 = 0.f, a3 = 0.f, den = 0.f;
    for (int p0 = beg; p0 < end; p0 += 32) {
        const int  m     = min(32, end - p0);
        const bool valid = (p0 + lane < end);
        const int   sl = valid ? g_es[p0 + lane] : 0;
        const float wl = valid ? __expf(lrelu(g_as2[sl] + ad)) : 0.f;
        int j = 0;
        for (; j + 4 <= m; j += 4) {
            const int   s0 = __shfl_sync(FULL, sl, j);
            const int   s1 = __shfl_sync(FULL, sl, j + 1);
            const int   s2 = __shfl_sync(FULL, sl, j + 2);
            const int   s3 = __shfl_sync(FULL, sl, j + 3);
            const float w0 = __shfl_sync(FULL, wl, j);
            const float w1 = __shfl_sync(FULL, wl, j + 1);
            const float w2 = __shfl_sync(FULL, wl, j + 2);
            const float w3 = __shfl_sync(FULL, wl, j + 3);
            a0 += w0 * __half2float(g_h2h[s0 * HID + lane]);
            a1 += w1 * __half2float(g_h2h[s1 * HID + lane]);
            a2 += w2 * __half2float(g_h2h[s2 * HID + lane]);
            a3 += w3 * __half2float(g_h2h[s3 * HID + lane]);
            den += (w0 + w1) + (w2 + w3);
        }
        for (; j < m; j++) {
            const int   s0 = __shfl_sync(FULL, sl, j);
            const float w0 = __shfl_sync(FULL, wl, j);
            a0 += w0 * __half2float(g_h2h[s0 * HID + lane]);
            den += w0;
        }
    }
    const float acc = (a0 + a1) + (a2 + a3);
    const float v = fmaxf(acc / den + b2[lane], 0.f);
    const int g = batch[di];
    atomicAdd(&g_psum[g * HID + lane], v);
    if (lane == 0) atomicAdd(&g_cnt[g], 1.f);
}

// ---------------- K8: final FC ----------------
__global__ void k8_fc(const float* __restrict__ fcw, const float* __restrict__ fcb,
                      float* __restrict__ out) {
    const int tid = threadIdx.x;
    if (tid >= GG * OUTD) return;
    const int g = tid / OUTD, o = tid % OUTD;
    const float inv = 1.f / fmaxf(g_cnt[g], 1.f);
    float acc = fcb[o];
    #pragma unroll
    for (int c = 0; c < HID; c++)
        acc += g_psum[g * HID + c] * inv * fcw[c * OUTD + o];
    out[tid] = acc;
}

// ---------------- K_CLEANUP: restore zero-state for next replay ----------
__global__ void k_cleanup() {
    const int i = blockIdx.x * blockDim.x + threadIdx.x;
    if (i < NN) g_deg[i] = 0;
    if (i < GG * HID) g_psum[i] = 0.f;
    if (i < GG) g_cnt[i] = 0.f;
    if (i < NB) g_stat[i] = 0ull;
    if (i == 0) g_tilectr = 0;
}

// ---------------- launch ----------------
extern "C" void kernel_launch(void* const* d_in, const int* in_sizes, int n_in,
                              void* d_out, int out_size) {
    const float* x    = (const float*)d_in[0];
    const int*   esrc = (const int*)  d_in[1];
    const int*   edst = (const int*)  d_in[2];
    const int*   batch= (const int*)  d_in[3];
    const float* W1   = (const float*)d_in[4];
    const float* as1  = (const float*)d_in[5];
    const float* ad1  = (const float*)d_in[6];
    const float* b1   = (const float*)d_in[7];
    const float* W2   = (const float*)d_in[8];
    const float* as2  = (const float*)d_in[9];
    const float* ad2  = (const float*)d_in[10];
    const float* b2   = (const float*)d_in[11];
    const float* fcw  = (const float*)d_in[12];
    const float* fcb  = (const float*)d_in[13];
    float* out = (float*)d_out;

    // one-time host resources (not device memory; identical launch DAG every call)
    static cudaStream_t s_csr = nullptr;
    static cudaEvent_t  ev_fork = nullptr, ev_join = nullptr;
    if (s_csr == nullptr) {
        cudaStreamCreateWithFlags(&s_csr, cudaStreamNonBlocking);
        cudaEventCreateWithFlags(&ev_fork, cudaEventDisableTiming);
        cudaEventCreateWithFlags(&ev_join, cudaEventDisableTiming);
    }

    // diagnostic: single mma.sync (writes g_probe only)
    k_probe<<<1, 32>>>();

    // fork: CSR chain on s_csr; feature GEMM on default stream
    cudaEventRecord(ev_fork, 0);
    cudaStreamWaitEvent(s_csr, ev_fork, 0);

    k_count  <<<(EE + 255) / 256, 256, 0, s_csr>>>(edst);
    k_scan   <<<NB, 256, 0, s_csr>>>();
    k_scatter<<<(ET + 255) / 256, 256, 0, s_csr>>>(esrc, edst);
    cudaEventRecord(ev_join, s_csr);

    k1_gemm1 <<<(NN + 31) / 32, 128>>>(x, W1, as1, ad1);

    // join: aggregation needs both CSR and h1/as1/ad1
    cudaStreamWaitEvent(0, ev_join, 0);

    k_agg1   <<<(NN + 7) / 8, 256>>>(b1);
    k4_gemm2 <<<(NN + 31) / 32, 256>>>(W2, as2, ad2);
    k_agg2   <<<(NN + 7) / 8, 256>>>(batch, b2);
    k8_fc    <<<1, 640>>>(fcw, fcb, out);
    k_cleanup<<<(NN + 255) / 256, 256>>>();
}

// round 15
// speedup vs baseline: 2.2458x; 1.1519x over previous
#include <cuda_runtime.h>
#include <cuda_fp16.h>
#include <cstdint>

// ---------------- problem constants ----------------
#define NN    50000
#define NNP   50048         // padded to multiple of 64 (GEMM M-tiles)
#define EE    800000
#define ET    (EE + NN)     // edges + self loops
#define GG    64
#define FIN   128
#define HID   32
#define HEADS 4
#define F1    (HEADS * HID) // 128
#define OUTD  10
#define NEG   0.2f
#define FULL  0xffffffffu
#define NB    196           // scan blocks: 196*256 = 50176 >= NN

// ---------------- device scratch (no allocations; zero-init at load) -----
__device__ __half g_xh [NNP * FIN];     // x in fp16 (padded rows stay zero)
__device__ __half g_w1t[F1 * FIN];      // W1^T: [n][k]
__device__ __half g_w2t[HID * F1];      // W2^T: [n][k]
__device__ __half g_h1h[NNP * F1];      // layer-1 features (fp16)
__device__ float  g_as1 [NN * HEADS];
__device__ float  g_ad1 [NN * HEADS];
__device__ __half g_x2h [NNP * F1];     // relu(agg1+b1) fp16 (padded rows zero)
__device__ __half g_h2h [NNP * HID];    // layer-2 features (fp16)
__device__ float  g_as2 [NN];
__device__ float  g_ad2 [NN];
__device__ float  g_psum[GG * HID];     // zero at load; re-zeroed by k_cleanup
__device__ float  g_cnt [GG];
// CSR-by-destination
__device__ int    g_deg   [NN];         // zero at load; re-zeroed by k_cleanup
__device__ int    g_cursor[NN];
__device__ int    g_rs    [NN + 1];
__device__ int    g_es    [ET];
// decoupled-lookback scan state
__device__ unsigned long long g_stat[NB];
__device__ int    g_tilectr;

__device__ __forceinline__ float lrelu(float v) { return v > 0.f ? v : NEG * v; }

// mma asm emitted ONLY via macro on named body-local scalars (probe-proven
// pattern; NO function boundary around accumulators -> registers, no lmem).
#define MMA16816(C0,C1,C2,C3,A0,A1,A2,A3,B0,B1)                               \
    asm volatile(                                                             \
        "mma.sync.aligned.m16n8k16.row.col.f32.f16.f16.f32 "                  \
        "{%0,%1,%2,%3}, {%4,%5,%6,%7}, {%8,%9}, {%0,%1,%2,%3};\n"             \
        : "+f"(C0), "+f"(C1), "+f"(C2), "+f"(C3)                              \
        : "r"(A0), "r"(A1), "r"(A2), "r"(A3), "r"(B0), "r"(B1))

// ---------------- K0b: count in-degree (deg starts zeroed) ---------------
__global__ void k_count(const int* __restrict__ dst) {
    const int e = blockIdx.x * blockDim.x + threadIdx.x;
    if (e < EE) atomicAdd(&g_deg[dst[e]], 1);
}

// ---------------- scan: single-kernel decoupled lookback -----------------
__global__ void k_scan() {
    __shared__ int sbid;
    __shared__ int ws[8];
    __shared__ int s_prefix;
    const int tid = threadIdx.x, lane = tid & 31, wid = tid >> 5;
    if (tid == 0) sbid = atomicAdd(&g_tilectr, 1);
    __syncthreads();
    const int bid = sbid;
    const int i   = bid * 256 + tid;
    const int v   = (i < NN) ? (g_deg[i] + 1) : 0;   // +1 = self loop

    int s = v;
    #pragma unroll
    for (int o = 1; o < 32; o <<= 1) {
        const int t = __shfl_up_sync(FULL, s, o);
        if (lane >= o) s += t;
    }
    if (lane == 31) ws[wid] = s;
    __syncthreads();
    if (wid == 0) {
        int t = (lane < 8) ? ws[lane] : 0;
        #pragma unroll
        for (int o = 1; o < 8; o <<= 1) {
            const int u = __shfl_up_sync(FULL, t, o);
            if (lane >= o) t += u;
        }
        if (lane < 8) ws[lane] = t;
    }
    __syncthreads();
    const int incl  = (wid ? ws[wid - 1] : 0) + s;
    const int total = ws[7];

    if (tid == 0) {
        if (bid > 0)
            atomicExch(&g_stat[bid], (1ull << 32) | (unsigned int)total);
        int prefix = 0;
        if (bid > 0) {
            int k = bid - 1;
            while (true) {
                unsigned long long st;
                do { st = *(volatile unsigned long long*)&g_stat[k]; }
                while ((st >> 32) == 0ull);
                prefix += (int)(unsigned int)(st & 0xffffffffull);
                if ((st >> 32) == 2ull) break;
                k--;
            }
        }
        s_prefix = prefix;
        atomicExch(&g_stat[bid], (2ull << 32) | (unsigned int)(prefix + total));
    }
    __syncthreads();
    const int base = s_prefix;
    if (i < NN) {
        g_rs[i + 1] = base + incl;
        g_cursor[i] = base + incl - v;
    }
    if (i == 0) g_rs[0] = 0;
}

// ---------------- K_SCAT: pure CSR permutation ----------------
__global__ void k_scatter(const int* __restrict__ src, const int* __restrict__ dst) {
    const int e = blockIdx.x * blockDim.x + threadIdx.x;
    if (e >= ET) return;
    int si, di;
    if (e < EE) { si = src[e]; di = dst[e]; }
    else        { si = di = e - EE; }
    g_es[atomicAdd(&g_cursor[di], 1)] = si;
}

// ---------------- conversions ----------------
__global__ void k_cvtx(const float* __restrict__ x) {
    const int i = blockIdx.x * blockDim.x + threadIdx.x;   // float4 index
    if (i >= NN * FIN / 4) return;
    const float4 v = ((const float4*)x)[i];
    __half2* o = (__half2*)g_xh;
    o[i * 2 + 0] = __float22half2_rn(make_float2(v.x, v.y));
    o[i * 2 + 1] = __float22half2_rn(make_float2(v.z, v.w));
}

__global__ void k_cvtw(const float* __restrict__ W1, const float* __restrict__ W2) {
    const int t = blockIdx.x * blockDim.x + threadIdx.x;   // 64*256 = 16384
    if (t < F1 * FIN) {
        const int n = t >> 7, k = t & 127;
        g_w1t[t] = __float2half(W1[k * F1 + n]);
    }
    if (t < HID * F1) {
        const int n = t >> 7, k = t & 127;
        g_w2t[t] = __float2half(W2[k * HID + n]);
    }
}

// ---------------- TC GEMM 1: h1[M,128] = xh[M,128] @ w1t[128,128]^T ------
// 512 threads / 16 warps: wr = w&3 (16-row group), wc = w>>2 (32-col quarter).
// 16 named scalar accumulators; asm via macro in body; unroll 2 k-loop.
__global__ __launch_bounds__(512) void k_gemm1_tc() {
    __shared__ __half as[64][136];
    const int m0  = blockIdx.x * 64;
    const int tid = threadIdx.x, lane = tid & 31, w = tid >> 5;
    const int wr  = w & 3, wc = w >> 2;

    {   // load A tile 64x128 = 1024 uint4: 512 threads x 2
        const uint4* srcA = (const uint4*)(g_xh + (size_t)m0 * FIN);
        const int u0 = tid, u1 = tid + 512;
        const int r0_ = u0 >> 4, c0_ = (u0 & 15) << 3;
        const int r1_ = u1 >> 4, c1_ = (u1 & 15) << 3;
        *(uint4*)&as[r0_][c0_] = srcA[u0];
        *(uint4*)&as[r1_][c1_] = srcA[u1];
    }
    __syncthreads();

    const int g  = lane >> 2, tg = lane & 3;
    const int row = wr * 16 + g;
    const int nbase = wc * 32;

    float c00 = 0.f, c01 = 0.f, c02 = 0.f, c03 = 0.f;
    float c10 = 0.f, c11 = 0.f, c12 = 0.f, c13 = 0.f;
    float c20 = 0.f, c21 = 0.f, c22 = 0.f, c23 = 0.f;
    float c30 = 0.f, c31 = 0.f, c32 = 0.f, c33 = 0.f;

    #pragma unroll 2
    for (int kt = 0; kt < 8; kt++) {
        const int kb = kt * 16 + tg * 2;
        const uint32_t a0 = *(const uint32_t*)&as[row][kb];
        const uint32_t a1 = *(const uint32_t*)&as[row + 8][kb];
        const uint32_t a2 = *(const uint32_t*)&as[row][kb + 8];
        const uint32_t a3 = *(const uint32_t*)&as[row + 8][kb + 8];
        const __half* bp0 = g_w1t + (size_t)(nbase + g) * FIN + kb;
        const __half* bp1 = bp0 + 8 * FIN;
        const __half* bp2 = bp0 + 16 * FIN;
        const __half* bp3 = bp0 + 24 * FIN;
        const uint32_t b00 = *(const uint32_t*)bp0, b01 = *(const uint32_t*)(bp0 + 8);
        const uint32_t b10 = *(const uint32_t*)bp1, b11 = *(const uint32_t*)(bp1 + 8);
        const uint32_t b20 = *(const uint32_t*)bp2, b21 = *(const uint32_t*)(bp2 + 8);
        const uint32_t b30 = *(const uint32_t*)bp3, b31 = *(const uint32_t*)(bp3 + 8);
        MMA16816(c00, c01, c02, c03, a0, a1, a2, a3, b00, b01);
        MMA16816(c10, c11, c12, c13, a0, a1, a2, a3, b10, b11);
        MMA16816(c20, c21, c22, c23, a0, a1, a2, a3, b20, b21);
        MMA16816(c30, c31, c32, c33, a0, a1, a2, a3, b30, b31);
    }

    const int r0 = m0 + row;
    const int cb = nbase + tg * 2;
    *(__half2*)&g_h1h[(size_t)r0 * F1 + cb]            = __float22half2_rn(make_float2(c00, c01));
    *(__half2*)&g_h1h[(size_t)(r0 + 8) * F1 + cb]      = __float22half2_rn(make_float2(c02, c03));
    *(__half2*)&g_h1h[(size_t)r0 * F1 + cb + 8]        = __float22half2_rn(make_float2(c10, c11));
    *(__half2*)&g_h1h[(size_t)(r0 + 8) * F1 + cb + 8]  = __float22half2_rn(make_float2(c12, c13));
    *(__half2*)&g_h1h[(size_t)r0 * F1 + cb + 16]       = __float22half2_rn(make_float2(c20, c21));
    *(__half2*)&g_h1h[(size_t)(r0 + 8) * F1 + cb + 16] = __float22half2_rn(make_float2(c22, c23));
    *(__half2*)&g_h1h[(size_t)r0 * F1 + cb + 24]       = __float22half2_rn(make_float2(c30, c31));
    *(__half2*)&g_h1h[(size_t)(r0 + 8) * F1 + cb + 24] = __float22half2_rn(make_float2(c32, c33));
}

// ---------------- TC GEMM 2: h2[M,32] = x2h[M,128] @ w2t[32,128]^T -------
// 512 threads / 16 warps: wr = w&3, wc = w>>2 (8-col quarter); 4 accumulators.
__global__ __launch_bounds__(512) void k_gemm2_tc() {
    __shared__ __half as[64][136];
    const int m0  = blockIdx.x * 64;
    const int tid = threadIdx.x, lane = tid & 31, w = tid >> 5;
    const int wr  = w & 3, wc = w >> 2;

    {   // load A tile 64x128 = 1024 uint4: 512 threads x 2
        const uint4* srcA = (const uint4*)(g_x2h + (size_t)m0 * FIN);
        const int u0 = tid, u1 = tid + 512;
        const int r0_ = u0 >> 4, c0_ = (u0 & 15) << 3;
        const int r1_ = u1 >> 4, c1_ = (u1 & 15) << 3;
        *(uint4*)&as[r0_][c0_] = srcA[u0];
        *(uint4*)&as[r1_][c1_] = srcA[u1];
    }
    __syncthreads();

    const int g  = lane >> 2, tg = lane & 3;
    const int row = wr * 16 + g;
    const int nbase = wc * 8;

    float c00 = 0.f, c01 = 0.f, c02 = 0.f, c03 = 0.f;

    #pragma unroll 2
    for (int kt = 0; kt < 8; kt++) {
        const int kb = kt * 16 + tg * 2;
        const uint32_t a0 = *(const uint32_t*)&as[row][kb];
        const uint32_t a1 = *(const uint32_t*)&as[row + 8][kb];
        const uint32_t a2 = *(const uint32_t*)&as[row][kb + 8];
        const uint32_t a3 = *(const uint32_t*)&as[row + 8][kb + 8];
        const __half* bp0 = g_w2t + (size_t)(nbase + g) * FIN + kb;
        const uint32_t b00 = *(const uint32_t*)bp0, b01 = *(const uint32_t*)(bp0 + 8);
        MMA16816(c00, c01, c02, c03, a0, a1, a2, a3, b00, b01);
    }

    const int r0 = m0 + row;
    const int cb = nbase + tg * 2;
    *(__half2*)&g_h2h[(size_t)r0 * HID + cb]       = __float22half2_rn(make_float2(c00, c01));
    *(__half2*)&g_h2h[(size_t)(r0 + 8) * HID + cb] = __float22half2_rn(make_float2(c02, c03));
}

// ---------------- attention dots, layer 1 (warp per node) ----------------
__global__ void k_att1(const float* __restrict__ as_in, const float* __restrict__ ad_in) {
    const int n    = blockIdx.x * 8 + (threadIdx.x >> 5);
    const int lane = threadIdx.x & 31;
    if (n >= NN) return;
    const uint2 u = *(const uint2*)&g_h1h[(size_t)n * F1 + lane * 4];
    const float2 f0 = __half22float2(*(const __half2*)&u.x);
    const float2 f1 = __half22float2(*(const __half2*)&u.y);
    const int c = lane * 4;
    float s = f0.x * as_in[c] + f0.y * as_in[c + 1] + f1.x * as_in[c + 2] + f1.y * as_in[c + 3];
    float d = f0.x * ad_in[c] + f0.y * ad_in[c + 1] + f1.x * ad_in[c + 2] + f1.y * ad_in[c + 3];
    #pragma unroll
    for (int o = 1; o < 8; o <<= 1) {
        s += __shfl_xor_sync(FULL, s, o);
        d += __shfl_xor_sync(FULL, d, o);
    }
    if ((lane & 7) == 0) {
        const int h = lane >> 3;
        g_as1[n * HEADS + h] = s;
        g_ad1[n * HEADS + h] = d;
    }
}

// ---------------- attention dots, layer 2 (warp per node) ----------------
__global__ void k_att2(const float* __restrict__ as_in, const float* __restrict__ ad_in) {
    const int n    = blockIdx.x * 8 + (threadIdx.x >> 5);
    const int lane = threadIdx.x & 31;
    if (n >= NN) return;
    const float h = __half2float(g_h2h[(size_t)n * HID + lane]);
    float s = h * as_in[lane];
    float d = h * ad_in[lane];
    #pragma unroll
    for (int o = 1; o < 32; o <<= 1) {
        s += __shfl_xor_sync(FULL, s, o);
        d += __shfl_xor_sync(FULL, d, o);
    }
    if (lane == 0) { g_as2[n] = s; g_ad2[n] = d; }
}

// ---------------- K_AGG1: gather layer 1, in-register edge weights -------
__global__ void k_agg1(const float* __restrict__ b1) {
    const int di   = blockIdx.x * 8 + (threadIdx.x >> 5);
    const int lane = threadIdx.x & 31;
    if (di >= NN) return;
    const int beg = g_rs[di], end = g_rs[di + 1];
    const int h8   = lane >> 3;
    const int hsel = lane & 3;
    const int esel = lane >> 2;
    const float adv = g_ad1[di * 4 + hsel];

    float ax = 0.f, ay = 0.f, az = 0.f, aw = 0.f, den = 0.f;

    for (int p0 = beg; p0 < end; p0 += 32) {
        const int m  = min(32, end - p0);
        const int sl = (p0 + lane < end) ? g_es[p0 + lane] : 0;
        const int nc = (m + 7) >> 3;
        for (int c = 0; c < nc; c++) {
            const int base = c * 8;
            const int  sle = __shfl_sync(FULL, sl, base + esel);
            float w = 0.f;
            if (p0 + base + esel < end)
                w = __expf(lrelu(g_as1[sle * 4 + hsel] + adv));
            den += w;
            const int mm = m - base;
            if (mm >= 8) {
                #pragma unroll
                for (int j = 0; j < 8; j++) {
                    const int   si = __shfl_sync(FULL, sl, base + j);
                    const float wj = __shfl_sync(FULL, w, j * 4 + h8);
                    const uint2 u  = *(const uint2*)&g_h1h[(size_t)si * F1 + lane * 4];
                    const float2 f0 = __half22float2(*(const __half2*)&u.x);
                    const float2 f1 = __half22float2(*(const __half2*)&u.y);
                    ax += wj * f0.x; ay += wj * f0.y; az += wj * f1.x; aw += wj * f1.y;
                }
            } else {
                for (int j = 0; j < mm; j++) {
                    const int   si = __shfl_sync(FULL, sl, base + j);
                    const float wj = __shfl_sync(FULL, w, j * 4 + h8);
                    const uint2 u  = *(const uint2*)&g_h1h[(size_t)si * F1 + lane * 4];
                    const float2 f0 = __half22float2(*(const __half2*)&u.x);
                    const float2 f1 = __half22float2(*(const __half2*)&u.y);
                    ax += wj * f0.x; ay += wj * f0.y; az += wj * f1.x; aw += wj * f1.y;
                }
            }
        }
    }
    den += __shfl_xor_sync(FULL, den, 4);
    den += __shfl_xor_sync(FULL, den, 8);
    den += __shfl_xor_sync(FULL, den, 16);
    const float denF = __shfl_sync(FULL, den, h8);

    const float4 bb = *(const float4*)&b1[lane * 4];
    const float inv = 1.f / denF;
    const float ox = fmaxf(ax * inv + bb.x, 0.f);
    const float oy = fmaxf(ay * inv + bb.y, 0.f);
    const float oz = fmaxf(az * inv + bb.z, 0.f);
    const float ow = fmaxf(aw * inv + bb.w, 0.f);
    const __half2 p0 = __float22half2_rn(make_float2(ox, oy));
    const __half2 p1 = __float22half2_rn(make_float2(oz, ow));
    uint2 st;
    st.x = *(const uint32_t*)&p0;
    st.y = *(const uint32_t*)&p1;
    *(uint2*)&g_x2h[(size_t)di * F1 + lane * 4] = st;
}

// ---------------- K_AGG2: gather layer 2 (fused weights) + mean-pool -----
__global__ void k_agg2(const int* __restrict__ batch, const float* __restrict__ b2) {
    const int di   = blockIdx.x * 8 + (threadIdx.x >> 5);
    const int lane = threadIdx.x & 31;
    if (di >= NN) return;
    const int   beg = g_rs[di], end = g_rs[di + 1];
    const float ad  = g_ad2[di];

    float a0 = 0.f, a1 = 0.f, a2 = 0.f, a3 = 0.f, den = 0.f;
    for (int p0 = beg; p0 < end; p0 += 32) {
        const int  m     = min(32, end - p0);
        const bool valid = (p0 + lane < end);
        const int   sl = valid ? g_es[p0 + lane] : 0;
        const float wl = valid ? __expf(lrelu(g_as2[sl] + ad)) : 0.f;
        int j = 0;
        for (; j + 4 <= m; j += 4) {
            const int   s0 = __shfl_sync(FULL, sl, j);
            const int   s1 = __shfl_sync(FULL, sl, j + 1);
            const int   s2 = __shfl_sync(FULL, sl, j + 2);
            const int   s3 = __shfl_sync(FULL, sl, j + 3);
            const float w0 = __shfl_sync(FULL, wl, j);
            const float w1 = __shfl_sync(FULL, wl, j + 1);
            const float w2 = __shfl_sync(FULL, wl, j + 2);
            const float w3 = __shfl_sync(FULL, wl, j + 3);
            a0 += w0 * __half2float(g_h2h[(size_t)s0 * HID + lane]);
            a1 += w1 * __half2float(g_h2h[(size_t)s1 * HID + lane]);
            a2 += w2 * __half2float(g_h2h[(size_t)s2 * HID + lane]);
            a3 += w3 * __half2float(g_h2h[(size_t)s3 * HID + lane]);
            den += (w0 + w1) + (w2 + w3);
        }
        for (; j < m; j++) {
            const int   s0 = __shfl_sync(FULL, sl, j);
            const float w0 = __shfl_sync(FULL, wl, j);
            a0 += w0 * __half2float(g_h2h[(size_t)s0 * HID + lane]);
            den += w0;
        }
    }
    const float acc = (a0 + a1) + (a2 + a3);
    const float v = fmaxf(acc / den + b2[lane], 0.f);
    const int g = batch[di];
    atomicAdd(&g_psum[g * HID + lane], v);
    if (lane == 0) atomicAdd(&g_cnt[g], 1.f);
}

// ---------------- K8: final FC ----------------
__global__ void k8_fc(const float* __restrict__ fcw, const float* __restrict__ fcb,
                      float* __restrict__ out) {
    const int tid = threadIdx.x;
    if (tid >= GG * OUTD) return;
    const int g = tid / OUTD, o = tid % OUTD;
    const float inv = 1.f / fmaxf(g_cnt[g], 1.f);
    float acc = fcb[o];
    #pragma unroll
    for (int c = 0; c < HID; c++)
        acc += g_psum[g * HID + c] * inv * fcw[c * OUTD + o];
    out[tid] = acc;
}

// ---------------- K_CLEANUP: restore zero-state for next replay ----------
__global__ void k_cleanup() {
    const int i = blockIdx.x * blockDim.x + threadIdx.x;
    if (i < NN) g_deg[i] = 0;
    if (i < GG * HID) g_psum[i] = 0.f;
    if (i < GG) g_cnt[i] = 0.f;
    if (i < NB) g_stat[i] = 0ull;
    if (i == 0) g_tilectr = 0;
}

// ---------------- launch ----------------
extern "C" void kernel_launch(void* const* d_in, const int* in_sizes, int n_in,
                              void* d_out, int out_size) {
    const float* x    = (const float*)d_in[0];
    const int*   esrc = (const int*)  d_in[1];
    const int*   edst = (const int*)  d_in[2];
    const int*   batch= (const int*)  d_in[3];
    const float* W1   = (const float*)d_in[4];
    const float* as1  = (const float*)d_in[5];
    const float* ad1  = (const float*)d_in[6];
    const float* b1   = (const float*)d_in[7];
    const float* W2   = (const float*)d_in[8];
    const float* as2  = (const float*)d_in[9];
    const float* ad2  = (const float*)d_in[10];
    const float* b2   = (const float*)d_in[11];
    const float* fcw  = (const float*)d_in[12];
    const float* fcb  = (const float*)d_in[13];
    float* out = (float*)d_out;

    // one-time host resources (not device memory; identical launch DAG every call)
    static cudaStream_t s_csr = nullptr;
    static cudaEvent_t  ev_fork = nullptr, ev_join = nullptr;
    if (s_csr == nullptr) {
        cudaStreamCreateWithFlags(&s_csr, cudaStreamNonBlocking);
        cudaEventCreateWithFlags(&ev_fork, cudaEventDisableTiming);
        cudaEventCreateWithFlags(&ev_join, cudaEventDisableTiming);
    }

    // fork: CSR chain on s_csr; conversions + GEMM path on default stream
    cudaEventRecord(ev_fork, 0);
    cudaStreamWaitEvent(s_csr, ev_fork, 0);

    k_count  <<<(EE + 255) / 256, 256, 0, s_csr>>>(edst);
    k_scan   <<<NB, 256, 0, s_csr>>>();
    k_scatter<<<(ET + 255) / 256, 256, 0, s_csr>>>(esrc, edst);
    cudaEventRecord(ev_join, s_csr);

    k_cvtx    <<<(NN * FIN / 4 + 255) / 256, 256>>>(x);
    k_cvtw    <<<64, 256>>>(W1, W2);
    k_gemm1_tc<<<NNP / 64, 512>>>();
    k_att1    <<<(NN + 7) / 8, 256>>>(as1, ad1);

    // join: aggregation needs both CSR and h1/as1/ad1
    cudaStreamWaitEvent(0, ev_join, 0);

    k_agg1    <<<(NN + 7) / 8, 256>>>(b1);
    k_gemm2_tc<<<NNP / 64, 512>>>();
    k_att2    <<<(NN + 7) / 8, 256>>>(as2, ad2);
    k_agg2    <<<(NN + 7) / 8, 256>>>(batch, b2);
    k8_fc     <<<1, 640>>>(fcw, fcb, out);
    k_cleanup <<<(NN + 255) / 256, 256>>>();
}

// round 16
// speedup vs baseline: 2.4057x; 1.0712x over previous
#include <cuda_runtime.h>
#include <cuda_fp16.h>
#include <cstdint>

// ---------------- problem constants ----------------
#define NN    50000
#define NNP   50048         // padded to multiple of 64 (GEMM M-tiles)
#define EE    800000
#define ET    (EE + NN)     // edges + self loops
#define GG    64
#define FIN   128
#define HID   32
#define HEADS 4
#define F1    (HEADS * HID) // 128
#define OUTD  10
#define NEG   0.2f
#define FULL  0xffffffffu
#define NB    196           // scan blocks: 196*256 = 50176 >= NN

// ---------------- device scratch (no allocations; zero-init at load) -----
__device__ __half g_w1t[F1 * FIN];      // W1^T: [n][k]
__device__ __half g_w2t[HID * F1];      // W2^T: [n][k]
__device__ __half g_h1h[NNP * F1];      // layer-1 features (fp16)
__device__ float  g_as1 [NN * HEADS];
__device__ float  g_ad1 [NN * HEADS];
__device__ __half g_x2h [NNP * F1];     // relu(agg1+b1) fp16 (padded rows zero)
__device__ __half g_h2h [NNP * HID];    // layer-2 features (fp16)
__device__ float  g_as2 [NN];
__device__ float  g_ad2 [NN];
__device__ float  g_psum[GG * HID];     // zero at load; re-zeroed by k_cleanup
__device__ float  g_cnt [GG];
// CSR-by-destination
__device__ int    g_deg   [NN];         // zero at load; re-zeroed by k_cleanup
__device__ int    g_cursor[NN];
__device__ int    g_rs    [NN + 1];
__device__ int    g_es    [ET];
// decoupled-lookback scan state
__device__ unsigned long long g_stat[NB];
__device__ int    g_tilectr;

__device__ __forceinline__ float lrelu(float v) { return v > 0.f ? v : NEG * v; }

// mma asm emitted ONLY via macro on named body-local scalars (probe-proven:
// no function boundary around accumulators -> registers, no lmem).
#define MMA16816(C0,C1,C2,C3,A0,A1,A2,A3,B0,B1)                               \
    asm volatile(                                                             \
        "mma.sync.aligned.m16n8k16.row.col.f32.f16.f16.f32 "                  \
        "{%0,%1,%2,%3}, {%4,%5,%6,%7}, {%8,%9}, {%0,%1,%2,%3};\n"             \
        : "+f"(C0), "+f"(C1), "+f"(C2), "+f"(C3)                              \
        : "r"(A0), "r"(A1), "r"(A2), "r"(A3), "r"(B0), "r"(B1))

// ---------------- K0b: count in-degree (deg starts zeroed) ---------------
__global__ void k_count(const int* __restrict__ dst) {
    const int e = blockIdx.x * blockDim.x + threadIdx.x;
    if (e < EE) atomicAdd(&g_deg[dst[e]], 1);
}

// ---------------- scan: single-kernel decoupled lookback -----------------
__global__ void k_scan() {
    __shared__ int sbid;
    __shared__ int ws[8];
    __shared__ int s_prefix;
    const int tid = threadIdx.x, lane = tid & 31, wid = tid >> 5;
    if (tid == 0) sbid = atomicAdd(&g_tilectr, 1);
    __syncthreads();
    const int bid = sbid;
    const int i   = bid * 256 + tid;
    const int v   = (i < NN) ? (g_deg[i] + 1) : 0;   // +1 = self loop

    int s = v;
    #pragma unroll
    for (int o = 1; o < 32; o <<= 1) {
        const int t = __shfl_up_sync(FULL, s, o);
        if (lane >= o) s += t;
    }
    if (lane == 31) ws[wid] = s;
    __syncthreads();
    if (wid == 0) {
        int t = (lane < 8) ? ws[lane] : 0;
        #pragma unroll
        for (int o = 1; o < 8; o <<= 1) {
            const int u = __shfl_up_sync(FULL, t, o);
            if (lane >= o) t += u;
        }
        if (lane < 8) ws[lane] = t;
    }
    __syncthreads();
    const int incl  = (wid ? ws[wid - 1] : 0) + s;
    const int total = ws[7];

    if (tid == 0) {
        if (bid > 0)
            atomicExch(&g_stat[bid], (1ull << 32) | (unsigned int)total);
        int prefix = 0;
        if (bid > 0) {
            int k = bid - 1;
            while (true) {
                unsigned long long st;
                do { st = *(volatile unsigned long long*)&g_stat[k]; }
                while ((st >> 32) == 0ull);
                prefix += (int)(unsigned int)(st & 0xffffffffull);
                if ((st >> 32) == 2ull) break;
                k--;
            }
        }
        s_prefix = prefix;
        atomicExch(&g_stat[bid], (2ull << 32) | (unsigned int)(prefix + total));
    }
    __syncthreads();
    const int base = s_prefix;
    if (i < NN) {
        g_rs[i + 1] = base + incl;
        g_cursor[i] = base + incl - v;
    }
    if (i == 0) g_rs[0] = 0;
}

// ---------------- K_SCAT: CSR permutation, 2 edges/thread (named scalars) -
__global__ void k_scatter(const int* __restrict__ src, const int* __restrict__ dst) {
    const int e0 = (blockIdx.x * blockDim.x + threadIdx.x) * 2;
    if (e0 >= ET) return;
    int si0, di0, si1, di1;
    if (e0 < EE) {              // EE even: pair never straddles boundary
        si0 = src[e0];     di0 = dst[e0];
        si1 = src[e0 + 1]; di1 = dst[e0 + 1];
    } else {
        si0 = di0 = e0 - EE;
        si1 = di1 = e0 + 1 - EE;
    }
    const int p0 = atomicAdd(&g_cursor[di0], 1);
    const int p1 = atomicAdd(&g_cursor[di1], 1);
    g_es[p0] = si0;
    g_es[p1] = si1;
}

// ---------------- weight conversion ----------------
__global__ void k_cvtw(const float* __restrict__ W1, const float* __restrict__ W2) {
    const int t = blockIdx.x * blockDim.x + threadIdx.x;   // 64*256 = 16384
    if (t < F1 * FIN) {
        const int n = t >> 7, k = t & 127;
        g_w1t[t] = __float2half(W1[k * F1 + n]);
    }
    if (t < HID * F1) {
        const int n = t >> 7, k = t & 127;
        g_w2t[t] = __float2half(W2[k * HID + n]);
    }
}

// ---------------- TC GEMM 1 (+fused x->fp16 conversion, +fused att dots) --
// 512 threads / 16 warps: wr = w&3 (16-row group), wc = w>>2 (32-col quarter).
// wc == head: each warp holds ALL 32 cols of head wc for its 16 rows, so the
// (row, head) attention dot reduces with 2 quad shfls -- no smem, no kernel.
__global__ __launch_bounds__(512) void k_gemm1_tc(
        const float* __restrict__ x,
        const float* __restrict__ as1, const float* __restrict__ ad1) {
    __shared__ __half as[64][136];
    const int m0  = blockIdx.x * 64;
    const int tid = threadIdx.x, lane = tid & 31, w = tid >> 5;
    const int wr  = w & 3, wc = w >> 2;

    // load A tile 64x128 floats -> fp16 smem: 2048 float4, 512 threads x 4
    {
        const float4* x4 = (const float4*)x;
        #pragma unroll
        for (int it = 0; it < 4; it++) {
            const int u  = it * 512 + tid;
            const int r  = u >> 5, c4 = u & 31;
            const int gr = m0 + r;
            float4 f = make_float4(0.f, 0.f, 0.f, 0.f);
            if (gr < NN) f = x4[(size_t)gr * 32 + c4];
            const __half2 h0 = __float22half2_rn(make_float2(f.x, f.y));
            const __half2 h1 = __float22half2_rn(make_float2(f.z, f.w));
            uint2 st;
            st.x = *(const uint32_t*)&h0;
            st.y = *(const uint32_t*)&h1;
            *(uint2*)&as[r][c4 * 4] = st;
        }
    }
    __syncthreads();

    const int g  = lane >> 2, tg = lane & 3;
    const int row = wr * 16 + g;
    const int nbase = wc * 32;

    float c00 = 0.f, c01 = 0.f, c02 = 0.f, c03 = 0.f;
    float c10 = 0.f, c11 = 0.f, c12 = 0.f, c13 = 0.f;
    float c20 = 0.f, c21 = 0.f, c22 = 0.f, c23 = 0.f;
    float c30 = 0.f, c31 = 0.f, c32 = 0.f, c33 = 0.f;

    #pragma unroll 2
    for (int kt = 0; kt < 8; kt++) {
        const int kb = kt * 16 + tg * 2;
        const uint32_t a0 = *(const uint32_t*)&as[row][kb];
        const uint32_t a1 = *(const uint32_t*)&as[row + 8][kb];
        const uint32_t a2 = *(const uint32_t*)&as[row][kb + 8];
        const uint32_t a3 = *(const uint32_t*)&as[row + 8][kb + 8];
        const __half* bp0 = g_w1t + (size_t)(nbase + g) * FIN + kb;
        const __half* bp1 = bp0 + 8 * FIN;
        const __half* bp2 = bp0 + 16 * FIN;
        const __half* bp3 = bp0 + 24 * FIN;
        const uint32_t b00 = *(const uint32_t*)bp0, b01 = *(const uint32_t*)(bp0 + 8);
        const uint32_t b10 = *(const uint32_t*)bp1, b11 = *(const uint32_t*)(bp1 + 8);
        const uint32_t b20 = *(const uint32_t*)bp2, b21 = *(const uint32_t*)(bp2 + 8);
        const uint32_t b30 = *(const uint32_t*)bp3, b31 = *(const uint32_t*)(bp3 + 8);
        MMA16816(c00, c01, c02, c03, a0, a1, a2, a3, b00, b01);
        MMA16816(c10, c11, c12, c13, a0, a1, a2, a3, b10, b11);
        MMA16816(c20, c21, c22, c23, a0, a1, a2, a3, b20, b21);
        MMA16816(c30, c31, c32, c33, a0, a1, a2, a3, b30, b31);
    }

    const int r0 = m0 + row;
    const int cb = nbase + tg * 2;
    *(__half2*)&g_h1h[(size_t)r0 * F1 + cb]            = __float22half2_rn(make_float2(c00, c01));
    *(__half2*)&g_h1h[(size_t)(r0 + 8) * F1 + cb]      = __float22half2_rn(make_float2(c02, c03));
    *(__half2*)&g_h1h[(size_t)r0 * F1 + cb + 8]        = __float22half2_rn(make_float2(c10, c11));
    *(__half2*)&g_h1h[(size_t)(r0 + 8) * F1 + cb + 8]  = __float22half2_rn(make_float2(c12, c13));
    *(__half2*)&g_h1h[(size_t)r0 * F1 + cb + 16]       = __float22half2_rn(make_float2(c20, c21));
    *(__half2*)&g_h1h[(size_t)(r0 + 8) * F1 + cb + 16] = __float22half2_rn(make_float2(c22, c23));
    *(__half2*)&g_h1h[(size_t)r0 * F1 + cb + 24]       = __float22half2_rn(make_float2(c30, c31));
    *(__half2*)&g_h1h[(size_t)(r0 + 8) * F1 + cb + 24] = __float22half2_rn(make_float2(c32, c33));

    // fused att1 dots: per (row, head=wc) quad-reduce across tg lanes
    const float av0 = as1[cb],      av1 = as1[cb + 1];
    const float av2 = as1[cb + 8],  av3 = as1[cb + 9];
    const float av4 = as1[cb + 16], av5 = as1[cb + 17];
    const float av6 = as1[cb + 24], av7 = as1[cb + 25];
    const float dv0 = ad1[cb],      dv1 = ad1[cb + 1];
    const float dv2 = ad1[cb + 8],  dv3 = ad1[cb + 9];
    const float dv4 = ad1[cb + 16], dv5 = ad1[cb + 17];
    const float dv6 = ad1[cb + 24], dv7 = ad1[cb + 25];

    float sA = c00*av0 + c01*av1 + c10*av2 + c11*av3 + c20*av4 + c21*av5 + c30*av6 + c31*av7;
    float dA = c00*dv0 + c01*dv1 + c10*dv2 + c11*dv3 + c20*dv4 + c21*dv5 + c30*dv6 + c31*dv7;
    float sB = c02*av0 + c03*av1 + c12*av2 + c13*av3 + c22*av4 + c23*av5 + c32*av6 + c33*av7;
    float dB = c02*dv0 + c03*dv1 + c12*dv2 + c13*dv3 + c22*dv4 + c23*dv5 + c32*dv6 + c33*dv7;
    #pragma unroll
    for (int o = 1; o < 4; o <<= 1) {
        sA += __shfl_xor_sync(FULL, sA, o);
        dA += __shfl_xor_sync(FULL, dA, o);
        sB += __shfl_xor_sync(FULL, sB, o);
        dB += __shfl_xor_sync(FULL, dB, o);
    }
    if (tg == 0) {
        if (r0 < NN)     { g_as1[r0 * HEADS + wc] = sA;       g_ad1[r0 * HEADS + wc] = dA; }
        if (r0 + 8 < NN) { g_as1[(r0 + 8) * HEADS + wc] = sB; g_ad1[(r0 + 8) * HEADS + wc] = dB; }
    }
}

// ---------------- TC GEMM 2 (+fused att2 dots via smem reduce) -----------
__global__ __launch_bounds__(512) void k_gemm2_tc(
        const float* __restrict__ as2, const float* __restrict__ ad2) {
    __shared__ __half as[64][136];
    __shared__ float reds[4][64];
    __shared__ float redd[4][64];
    const int m0  = blockIdx.x * 64;
    const int tid = threadIdx.x, lane = tid & 31, w = tid >> 5;
    const int wr  = w & 3, wc = w >> 2;

    {   // load A tile 64x128 fp16 = 1024 uint4: 512 threads x 2
        const uint4* srcA = (const uint4*)(g_x2h + (size_t)m0 * FIN);
        const int u0 = tid, u1 = tid + 512;
        const int r0_ = u0 >> 4, c0_ = (u0 & 15) << 3;
        const int r1_ = u1 >> 4, c1_ = (u1 & 15) << 3;
        *(uint4*)&as[r0_][c0_] = srcA[u0];
        *(uint4*)&as[r1_][c1_] = srcA[u1];
    }
    __syncthreads();

    const int g  = lane >> 2, tg = lane & 3;
    const int row = wr * 16 + g;
    const int nbase = wc * 8;

    float c00 = 0.f, c01 = 0.f, c02 = 0.f, c03 = 0.f;

    #pragma unroll 2
    for (int kt = 0; kt < 8; kt++) {
        const int kb = kt * 16 + tg * 2;
        const uint32_t a0 = *(const uint32_t*)&as[row][kb];
        const uint32_t a1 = *(const uint32_t*)&as[row + 8][kb];
        const uint32_t a2 = *(const uint32_t*)&as[row][kb + 8];
        const uint32_t a3 = *(const uint32_t*)&as[row + 8][kb + 8];
        const __half* bp0 = g_w2t + (size_t)(nbase + g) * FIN + kb;
        const uint32_t b00 = *(const uint32_t*)bp0, b01 = *(const uint32_t*)(bp0 + 8);
        MMA16816(c00, c01, c02, c03, a0, a1, a2, a3, b00, b01);
    }

    const int r0 = m0 + row;
    const int cb = nbase + tg * 2;
    *(__half2*)&g_h2h[(size_t)r0 * HID + cb]       = __float22half2_rn(make_float2(c00, c01));
    *(__half2*)&g_h2h[(size_t)(r0 + 8) * HID + cb] = __float22half2_rn(make_float2(c02, c03));

    // fused att2: quad-reduce within warp, cross-warp (wc) reduce via smem
    const float av0 = as2[cb], av1 = as2[cb + 1];
    const float dv0 = ad2[cb], dv1 = ad2[cb + 1];
    float sA = c00 * av0 + c01 * av1;
    float dA = c00 * dv0 + c01 * dv1;
    float sB = c02 * av0 + c03 * av1;
    float dB = c02 * dv0 + c03 * dv1;
    #pragma unroll
    for (int o = 1; o < 4; o <<= 1) {
        sA += __shfl_xor_sync(FULL, sA, o);
        dA += __shfl_xor_sync(FULL, dA, o);
        sB += __shfl_xor_sync(FULL, sB, o);
        dB += __shfl_xor_sync(FULL, dB, o);
    }
    if (tg == 0) {
        reds[wc][row]     = sA;  redd[wc][row]     = dA;
        reds[wc][row + 8] = sB;  redd[wc][row + 8] = dB;
    }
    __syncthreads();
    if (tid < 64) {
        const int n = m0 + tid;
        if (n < NN) {
            g_as2[n] = reds[0][tid] + reds[1][tid] + reds[2][tid] + reds[3][tid];
            g_ad2[n] = redd[0][tid] + redd[1][tid] + redd[2][tid] + redd[3][tid];
        }
    }
}

// ---------------- K_AGG1: gather layer 1, in-register edge weights -------
__global__ void k_agg1(const float* __restrict__ b1) {
    const int di   = blockIdx.x * 8 + (threadIdx.x >> 5);
    const int lane = threadIdx.x & 31;
    if (di >= NN) return;
    const int beg = g_rs[di], end = g_rs[di + 1];
    const int h8   = lane >> 3;
    const int hsel = lane & 3;
    const int esel = lane >> 2;
    const float adv = g_ad1[di * 4 + hsel];

    float ax = 0.f, ay = 0.f, az = 0.f, aw = 0.f, den = 0.f;

    for (int p0 = beg; p0 < end; p0 += 32) {
        const int m  = min(32, end - p0);
        const int sl = (p0 + lane < end) ? g_es[p0 + lane] : 0;
        const int nc = (m + 7) >> 3;
        for (int c = 0; c < nc; c++) {
            const int base = c * 8;
            const int  sle = __shfl_sync(FULL, sl, base + esel);
            float w = 0.f;
            if (p0 + base + esel < end)
                w = __expf(lrelu(g_as1[sle * 4 + hsel] + adv));
            den += w;
            const int mm = m - base;
            if (mm >= 8) {
                #pragma unroll
                for (int j = 0; j < 8; j++) {
                    const int   si = __shfl_sync(FULL, sl, base + j);
                    const float wj = __shfl_sync(FULL, w, j * 4 + h8);
                    const uint2 u  = *(const uint2*)&g_h1h[(size_t)si * F1 + lane * 4];
                    const float2 f0 = __half22float2(*(const __half2*)&u.x);
                    const float2 f1 = __half22float2(*(const __half2*)&u.y);
                    ax += wj * f0.x; ay += wj * f0.y; az += wj * f1.x; aw += wj * f1.y;
                }
            } else {
                for (int j = 0; j < mm; j++) {
                    const int   si = __shfl_sync(FULL, sl, base + j);
                    const float wj = __shfl_sync(FULL, w, j * 4 + h8);
                    const uint2 u  = *(const uint2*)&g_h1h[(size_t)si * F1 + lane * 4];
                    const float2 f0 = __half22float2(*(const __half2*)&u.x);
                    const float2 f1 = __half22float2(*(const __half2*)&u.y);
                    ax += wj * f0.x; ay += wj * f0.y; az += wj * f1.x; aw += wj * f1.y;
                }
            }
        }
    }
    den += __shfl_xor_sync(FULL, den, 4);
    den += __shfl_xor_sync(FULL, den, 8);
    den += __shfl_xor_sync(FULL, den, 16);
    const float denF = __shfl_sync(FULL, den, h8);

    const float4 bb = *(const float4*)&b1[lane * 4];
    const float inv = 1.f / denF;
    const float ox = fmaxf(ax * inv + bb.x, 0.f);
    const float oy = fmaxf(ay * inv + bb.y, 0.f);
    const float oz = fmaxf(az * inv + bb.z, 0.f);
    const float ow = fmaxf(aw * inv + bb.w, 0.f);
    const __half2 p0 = __float22half2_rn(make_float2(ox, oy));
    const __half2 p1 = __float22half2_rn(make_float2(oz, ow));
    uint2 st;
    st.x = *(const uint32_t*)&p0;
    st.y = *(const uint32_t*)&p1;
    *(uint2*)&g_x2h[(size_t)di * F1 + lane * 4] = st;
}

// ---------------- K_AGG2: gather layer 2 (fused weights) + mean-pool -----
__global__ void k_agg2(const int* __restrict__ batch, const float* __restrict__ b2) {
    const int di   = blockIdx.x * 8 + (threadIdx.x >> 5);
    const int lane = threadIdx.x & 31;
    if (di >= NN) return;
    const int   beg = g_rs[di], end = g_rs[di + 1];
    const float ad  = g_ad2[di];

    float a0 = 0.f, a1 = 0.f, a2 = 0.f, a3 = 0.f, den = 0.f;
    for (int p0 = beg; p0 < end; p0 += 32) {
        const int  m     = min(32, end - p0);
        const bool valid = (p0 + lane < end);
        const int   sl = valid ? g_es[p0 + lane] : 0;
        const float wl = valid ? __expf(lrelu(g_as2[sl] + ad)) : 0.f;
        int j = 0;
        for (; j + 4 <= m; j += 4) {
            const int   s0 = __shfl_sync(FULL, sl, j);
            const int   s1 = __shfl_sync(FULL, sl, j + 1);
            const int   s2 = __shfl_sync(FULL, sl, j + 2);
            const int   s3 = __shfl_sync(FULL, sl, j + 3);
            const float w0 = __shfl_sync(FULL, wl, j);
            const float w1 = __shfl_sync(FULL, wl, j + 1);
            const float w2 = __shfl_sync(FULL, wl, j + 2);
            const float w3 = __shfl_sync(FULL, wl, j + 3);
            a0 += w0 * __half2float(g_h2h[(size_t)s0 * HID + lane]);
            a1 += w1 * __half2float(g_h2h[(size_t)s1 * HID + lane]);
            a2 += w2 * __half2float(g_h2h[(size_t)s2 * HID + lane]);
            a3 += w3 * __half2float(g_h2h[(size_t)s3 * HID + lane]);
            den += (w0 + w1) + (w2 + w3);
        }
        for (; j < m; j++) {
            const int   s0 = __shfl_sync(FULL, sl, j);
            const float w0 = __shfl_sync(FULL, wl, j);
            a0 += w0 * __half2float(g_h2h[(size_t)s0 * HID + lane]);
            den += w0;
        }
    }
    const float acc = (a0 + a1) + (a2 + a3);
    const float v = fmaxf(acc / den + b2[lane], 0.f);
    const int g = batch[di];
    atomicAdd(&g_psum[g * HID + lane], v);
    if (lane == 0) atomicAdd(&g_cnt[g], 1.f);
}

// ---------------- K8: final FC ----------------
__global__ void k8_fc(const float* __restrict__ fcw, const float* __restrict__ fcb,
                      float* __restrict__ out) {
    const int tid = threadIdx.x;
    if (tid >= GG * OUTD) return;
    const int g = tid / OUTD, o = tid % OUTD;
    const float inv = 1.f / fmaxf(g_cnt[g], 1.f);
    float acc = fcb[o];
    #pragma unroll
    for (int c = 0; c < HID; c++)
        acc += g_psum[g * HID + c] * inv * fcw[c * OUTD + o];
    out[tid] = acc;
}

// ---------------- K_CLEANUP: restore zero-state for next replay ----------
__global__ void k_cleanup() {
    const int i = blockIdx.x * blockDim.x + threadIdx.x;
    if (i < NN) g_deg[i] = 0;
    if (i < GG * HID) g_psum[i] = 0.f;
    if (i < GG) g_cnt[i] = 0.f;
    if (i < NB) g_stat[i] = 0ull;
    if (i == 0) g_tilectr = 0;
}

// ---------------- launch ----------------
extern "C" void kernel_launch(void* const* d_in, const int* in_sizes, int n_in,
                              void* d_out, int out_size) {
    const float* x    = (const float*)d_in[0];
    const int*   esrc = (const int*)  d_in[1];
    const int*   edst = (const int*)  d_in[2];
    const int*   batch= (const int*)  d_in[3];
    const float* W1   = (const float*)d_in[4];
    const float* as1  = (const float*)d_in[5];
    const float* ad1  = (const float*)d_in[6];
    const float* b1   = (const float*)d_in[7];
    const float* W2   = (const float*)d_in[8];
    const float* as2  = (const float*)d_in[9];
    const float* ad2  = (const float*)d_in[10];
    const float* b2   = (const float*)d_in[11];
    const float* fcw  = (const float*)d_in[12];
    const float* fcb  = (const float*)d_in[13];
    float* out = (float*)d_out;

    // one-time host resources (not device memory; identical launch DAG every call)
    static cudaStream_t s_csr = nullptr;
    static cudaEvent_t  ev_fork = nullptr, ev_join = nullptr;
    if (s_csr == nullptr) {
        cudaStreamCreateWithFlags(&s_csr, cudaStreamNonBlocking);
        cudaEventCreateWithFlags(&ev_fork, cudaEventDisableTiming);
        cudaEventCreateWithFlags(&ev_join, cudaEventDisableTiming);
    }

    // fork: CSR chain on s_csr; weight cvt + GEMM path on default stream
    cudaEventRecord(ev_fork, 0);
    cudaStreamWaitEvent(s_csr, ev_fork, 0);

    k_count  <<<(EE + 255) / 256, 256, 0, s_csr>>>(edst);
    k_scan   <<<NB, 256, 0, s_csr>>>();
    k_scatter<<<(ET / 2 + 255) / 256, 256, 0, s_csr>>>(esrc, edst);
    cudaEventRecord(ev_join, s_csr);

    k_cvtw    <<<64, 256>>>(W1, W2);
    k_gemm1_tc<<<NNP / 64, 512>>>(x, as1, ad1);

    // join: aggregation needs both CSR and h1/as1/ad1
    cudaStreamWaitEvent(0, ev_join, 0);

    k_agg1    <<<(NN + 7) / 8, 256>>>(b1);
    k_gemm2_tc<<<NNP / 64, 512>>>(as2, ad2);
    k_agg2    <<<(NN + 7) / 8, 256>>>(batch, b2);
    k8_fc     <<<1, 640>>>(fcw, fcb, out);
    k_cleanup <<<(NN + 255) / 256, 256>>>();
}